// round 4
// baseline (speedup 1.0000x reference)
#include <cuda_runtime.h>
#include <cstdint>
#include <math.h>

#define DIMC 1024
#define BATCH 8
#define NHEADS 16
#define HDIM 64

// Scratch (static device arrays: allocation-free rule)
__device__ float g_qc[BATCH * DIMC * DIMC];
__device__ float g_kc[BATCH * DIMC * DIMC];
__device__ float g_vc[BATCH * DIMC * DIMC];
__device__ float g_ao[BATCH * DIMC * DIMC];

typedef unsigned long long ull;

__device__ __forceinline__ ull pack2(float lo, float hi) {
    ull r; asm("mov.b64 %0, {%1, %2};" : "=l"(r) : "f"(lo), "f"(hi)); return r;
}
__device__ __forceinline__ void unpack2(ull v, float &lo, float &hi) {
    asm("mov.b64 {%0, %1}, %2;" : "=f"(lo), "=f"(hi) : "l"(v));
}
__device__ __forceinline__ ull fma2(ull a, ull b, ull c) {
    ull d; asm("fma.rn.f32x2 %0, %1, %2, %3;" : "=l"(d) : "l"(a), "l"(b), "l"(c)); return d;
}

// ---------------------------------------------------------------------------
// Conv 3x3 SAME as implicit GEMM.
// Tile: 128 output channels x 64 spatial positions (8x8 pixel block).
// K loop: 8 input channels per step x 9 taps.
// grid: (16 spatial tiles, 8 o-tiles, 3 convs * 8 batches), block 256.
// ---------------------------------------------------------------------------
__global__ __launch_bounds__(256) void conv3x3_kernel(
    const float* __restrict__ qin, const float* __restrict__ kin, const float* __restrict__ vin,
    const float* __restrict__ Wq, const float* __restrict__ Wk, const float* __restrict__ Wv,
    const float* __restrict__ bq, const float* __restrict__ bk, const float* __restrict__ bv)
{
    __shared__ float Ws[128 * 73];   // [o][i*9+t], row padded to 73 (bank-safe reads)
    __shared__ float Xs[8 * 100];    // [i][10][10] halo patch

    const int tid = threadIdx.x;
    const int tx = tid & 15, ty = tid >> 4;
    const int b = blockIdx.z & 7;
    const int which = blockIdx.z >> 3;

    const float* xin; const float* w; const float* bias; float* out;
    if (which == 0)      { xin = qin; w = Wq; bias = bq; out = g_qc; }
    else if (which == 1) { xin = kin; w = Wk; bias = bk; out = g_kc; }
    else                 { xin = vin; w = Wv; bias = bv; out = g_vc; }
    xin += (size_t)b * DIMC * DIMC;
    out += (size_t)b * DIMC * DIMC;

    const int o0 = blockIdx.y * 128;
    const int st = blockIdx.x;
    const int y0 = (st >> 2) * 8, x0 = (st & 3) * 8;

    int xbase[4];
#pragma unroll
    for (int u = 0; u < 4; u++) { int p = tx + 16 * u; xbase[u] = (p >> 3) * 10 + (p & 7); }

    ull acc[8][2];
#pragma unroll
    for (int v = 0; v < 8; v++) { acc[v][0] = 0ull; acc[v][1] = 0ull; }

    for (int ic0 = 0; ic0 < DIMC; ic0 += 8) {
        // Load W chunk: 128 o x 72 (global contiguous per o-row, smem store conflict-free)
#pragma unroll
        for (int j = 0; j < 36; j++) {
            int idx = tid + 256 * j;           // 0..9215
            int o = idx / 72; int it = idx - o * 72;
            Ws[o * 73 + it] = w[(size_t)(o0 + o) * (DIMC * 9) + (size_t)ic0 * 9 + it];
        }
        // Load input patch 8ch x 10 x 10 with SAME-padding zeros
        for (int idx = tid; idx < 800; idx += 256) {
            int i = idx / 100; int rr = idx - i * 100; int r = rr / 10; int c = rr - r * 10;
            int y = y0 - 1 + r, xx = x0 - 1 + c;
            float vv = 0.f;
            if ((unsigned)y < 32u && (unsigned)xx < 32u)
                vv = xin[(size_t)(ic0 + i) * 1024 + y * 32 + xx];
            Xs[idx] = vv;
        }
        __syncthreads();

#pragma unroll 2
        for (int i = 0; i < 8; i++) {
#pragma unroll
            for (int t = 0; t < 9; t++) {
                const int off = i * 100 + (t / 3) * 10 + (t % 3);
                float xr0 = Xs[off + xbase[0]];
                float xr1 = Xs[off + xbase[1]];
                float xr2 = Xs[off + xbase[2]];
                float xr3 = Xs[off + xbase[3]];
                ull xa = pack2(xr0, xr1);
                ull xb = pack2(xr2, xr3);
#pragma unroll
                for (int v = 0; v < 8; v++) {
                    float wr = Ws[(ty + 16 * v) * 73 + i * 9 + t];
                    ull w2 = pack2(wr, wr);
                    acc[v][0] = fma2(w2, xa, acc[v][0]);
                    acc[v][1] = fma2(w2, xb, acc[v][1]);
                }
            }
        }
        __syncthreads();
    }

#pragma unroll
    for (int v = 0; v < 8; v++) {
        int o = o0 + ty + 16 * v;
        float bb = bias[o];
        float rs[4];
        unpack2(acc[v][0], rs[0], rs[1]);
        unpack2(acc[v][1], rs[2], rs[3]);
#pragma unroll
        for (int u = 0; u < 4; u++) {
            int p = tx + 16 * u;
            int y = y0 + (p >> 3), xx = x0 + (p & 7);
            out[(size_t)o * 1024 + y * 32 + xx] = rs[u] + bb;
        }
    }
}

// ---------------------------------------------------------------------------
// Flash-style attention over channel tokens. One block = 64 queries of one
// (batch, head). d = 64. Loops over 16 s-chunks of 64 with online softmax.
// smem: Q (rot-swizzled), K^T (rot-swizzled, later aliased by P), V. 48KB.
// grid: (16 t-tiles, 16 heads, 8 batches), block 256 (16x16).
// ---------------------------------------------------------------------------
__global__ __launch_bounds__(256) void attn_kernel(const int* __restrict__ mask)
{
    __shared__ float Qs[64 * 64];
    __shared__ float KPs[64 * 64];
    __shared__ float Vs[64 * 64];

    const int tid = threadIdx.x;
    const int tx = tid & 15, ty = tid >> 4;
    const int t0 = blockIdx.x * 64;
    const int hd = blockIdx.y;
    const int b  = blockIdx.z;

    const float* Qg = g_qc + (size_t)b * DIMC * DIMC + hd * HDIM;
    const float* Kg = g_kc + (size_t)b * DIMC * DIMC + hd * HDIM;
    const float* Vg = g_vc + (size_t)b * DIMC * DIMC + hd * HDIM;
    const int* mrow = mask + (size_t)b * DIMC * DIMC;

    // Load Q tile [t][d], rotation swizzle (d + t) & 63 for bank-safe row reads
    for (int idx = tid; idx < 4096; idx += 256) {
        int t = idx >> 6, d = idx & 63;
        Qs[t * 64 + ((d + t) & 63)] = Qg[(size_t)(t0 + t) * 1024 + d];
    }

    float m[4], l[4], acc[4][4];
#pragma unroll
    for (int a = 0; a < 4; a++) {
        m[a] = -INFINITY; l[a] = 0.f;
#pragma unroll
        for (int u = 0; u < 4; u++) acc[a][u] = 0.f;
    }

    const float scale = 0.125f;  // 1/sqrt(64)

    for (int s0 = 0; s0 < 1024; s0 += 64) {
        __syncthreads();  // previous PV reads done before overwriting K/V/P
        // K transposed into KPs[k][s], rotation swizzle (s + k) & 63.
        // FULL 64x64 tile: 4 reps x 256 threads x float4 = 4096 elements.
#pragma unroll
        for (int rep = 0; rep < 4; rep++) {
            int idx = tid + 256 * rep;        // 0..1023
            int s   = idx >> 4;               // 0..63
            int k4  = (idx & 15) * 4;         // 0..60
            const float4 kv = *(const float4*)(Kg + (size_t)(s0 + s) * 1024 + k4);
            KPs[(k4 + 0) * 64 + ((s + k4 + 0) & 63)] = kv.x;
            KPs[(k4 + 1) * 64 + ((s + k4 + 1) & 63)] = kv.y;
            KPs[(k4 + 2) * 64 + ((s + k4 + 2) & 63)] = kv.z;
            KPs[(k4 + 3) * 64 + ((s + k4 + 3) & 63)] = kv.w;
        }
        // V tile [s][d], direct layout, float4 loads
#pragma unroll
        for (int rep = 0; rep < 4; rep++) {
            int idx = tid + 256 * rep;        // 0..1023
            int s   = idx >> 4;
            int d4  = (idx & 15) * 4;
            const float4 vv = *(const float4*)(Vg + (size_t)(s0 + s) * 1024 + d4);
            *(float4*)(Vs + s * 64 + d4) = vv;
        }
        __syncthreads();

        // S = Q K^T for this thread's 4x4 (t, s) micro-tile
        float sv[4][4];
#pragma unroll
        for (int a = 0; a < 4; a++)
#pragma unroll
            for (int bb = 0; bb < 4; bb++) sv[a][bb] = 0.f;

#pragma unroll 8
        for (int k = 0; k < 64; k++) {
            float qr[4], kr[4];
#pragma unroll
            for (int a = 0; a < 4; a++) {
                int tr = ty + 16 * a;
                qr[a] = Qs[tr * 64 + ((k + tr) & 63)];
            }
#pragma unroll
            for (int bb = 0; bb < 4; bb++) {
                int sc = tx + 16 * bb;
                kr[bb] = KPs[k * 64 + ((sc + k) & 63)];
            }
#pragma unroll
            for (int a = 0; a < 4; a++)
#pragma unroll
                for (int bb = 0; bb < 4; bb++) sv[a][bb] += qr[a] * kr[bb];
        }

        // scale + mask (mask==0 -> -1e9, matching reference order)
#pragma unroll
        for (int a = 0; a < 4; a++) {
            int t = t0 + ty + 16 * a;
#pragma unroll
            for (int bb = 0; bb < 4; bb++) {
                int s = s0 + tx + 16 * bb;
                int mv = mrow[(size_t)t * 1024 + s];
                sv[a][bb] = (mv == 0) ? -1e9f : sv[a][bb] * scale;
            }
        }
        __syncthreads();  // all K reads complete before P overwrites KPs

        // Online softmax update + write P (rot-swizzled rows)
#pragma unroll
        for (int a = 0; a < 4; a++) {
            float rm = fmaxf(fmaxf(sv[a][0], sv[a][1]), fmaxf(sv[a][2], sv[a][3]));
            rm = fmaxf(rm, __shfl_xor_sync(0xffffffffu, rm, 1));
            rm = fmaxf(rm, __shfl_xor_sync(0xffffffffu, rm, 2));
            rm = fmaxf(rm, __shfl_xor_sync(0xffffffffu, rm, 4));
            rm = fmaxf(rm, __shfl_xor_sync(0xffffffffu, rm, 8));
            float mnew = fmaxf(m[a], rm);
            float fac = __expf(m[a] - mnew);
            float rsum = 0.f;
#pragma unroll
            for (int bb = 0; bb < 4; bb++) {
                float p = __expf(sv[a][bb] - mnew);
                sv[a][bb] = p;
                rsum += p;
            }
            rsum += __shfl_xor_sync(0xffffffffu, rsum, 1);
            rsum += __shfl_xor_sync(0xffffffffu, rsum, 2);
            rsum += __shfl_xor_sync(0xffffffffu, rsum, 4);
            rsum += __shfl_xor_sync(0xffffffffu, rsum, 8);
            l[a] = l[a] * fac + rsum;
            m[a] = mnew;
#pragma unroll
            for (int u = 0; u < 4; u++) acc[a][u] *= fac;
            int tr = ty + 16 * a;
#pragma unroll
            for (int bb = 0; bb < 4; bb++) {
                int sc = tx + 16 * bb;
                KPs[tr * 64 + ((sc + tr) & 63)] = sv[a][bb];
            }
        }
        __syncthreads();

        // O += P V
#pragma unroll 8
        for (int s = 0; s < 64; s++) {
            float pr[4], vr[4];
#pragma unroll
            for (int a = 0; a < 4; a++) {
                int tr = ty + 16 * a;
                pr[a] = KPs[tr * 64 + ((s + tr) & 63)];
            }
#pragma unroll
            for (int u = 0; u < 4; u++) vr[u] = Vs[s * 64 + tx + 16 * u];
#pragma unroll
            for (int a = 0; a < 4; a++)
#pragma unroll
                for (int u = 0; u < 4; u++) acc[a][u] += pr[a] * vr[u];
        }
    }

    float* og = g_ao + (size_t)b * DIMC * DIMC + hd * HDIM;
#pragma unroll
    for (int a = 0; a < 4; a++) {
        float inv = 1.f / l[a];
        int t = t0 + ty + 16 * a;
#pragma unroll
        for (int u = 0; u < 4; u++)
            og[(size_t)t * 1024 + tx + 16 * u] = acc[a][u] * inv;
    }
}

// ---------------------------------------------------------------------------
// Output projection: Y[row][j] = sum_c AO[row][c] * Wo[j][c] + bo[j]
// rows = 8192 (b,t). Tiles 64x64, BK=16. grid (16 j-tiles, 128 row-tiles).
// ---------------------------------------------------------------------------
__global__ __launch_bounds__(256) void proj_kernel(
    const float* __restrict__ Wo, const float* __restrict__ bo, float* __restrict__ out)
{
    __shared__ float As[64 * 17];  // [m][c], padded
    __shared__ float Bs[16 * 64];  // [c][j], transposed Wo tile

    const int tid = threadIdx.x;
    const int tx = tid & 15, ty = tid >> 4;
    const int j0 = blockIdx.x * 64;
    const int m0 = blockIdx.y * 64;

    float acc[4][4];
#pragma unroll
    for (int a = 0; a < 4; a++)
#pragma unroll
        for (int u = 0; u < 4; u++) acc[a][u] = 0.f;

    const float* A = g_ao;
    for (int c0 = 0; c0 < 1024; c0 += 16) {
        for (int idx = tid; idx < 1024; idx += 256) {
            int mm = idx >> 4, c = idx & 15;
            As[mm * 17 + c] = A[(size_t)(m0 + mm) * 1024 + c0 + c];
        }
        {
            int j = tid >> 2;
            int cq = (tid & 3) * 4;
            const float4 wv = *(const float4*)(Wo + (size_t)(j0 + j) * 1024 + c0 + cq);
            Bs[(cq + 0) * 64 + j] = wv.x;
            Bs[(cq + 1) * 64 + j] = wv.y;
            Bs[(cq + 2) * 64 + j] = wv.z;
            Bs[(cq + 3) * 64 + j] = wv.w;
        }
        __syncthreads();
#pragma unroll
        for (int c = 0; c < 16; c++) {
            float ar[4], br[4];
#pragma unroll
            for (int a = 0; a < 4; a++) ar[a] = As[(ty + 16 * a) * 17 + c];
#pragma unroll
            for (int u = 0; u < 4; u++) br[u] = Bs[c * 64 + tx + 16 * u];
#pragma unroll
            for (int a = 0; a < 4; a++)
#pragma unroll
                for (int u = 0; u < 4; u++) acc[a][u] += ar[a] * br[u];
        }
        __syncthreads();
    }

#pragma unroll
    for (int a = 0; a < 4; a++) {
        int row = m0 + ty + 16 * a;
#pragma unroll
        for (int u = 0; u < 4; u++) {
            int j = j0 + tx + 16 * u;
            out[(size_t)row * 1024 + j] = acc[a][u] + bo[j];
        }
    }
}

// ---------------------------------------------------------------------------
extern "C" void kernel_launch(void* const* d_in, const int* in_sizes, int n_in,
                              void* d_out, int out_size)
{
    const float* q   = (const float*)d_in[0];
    const float* k   = (const float*)d_in[1];
    const float* v   = (const float*)d_in[2];
    const float* Wq  = (const float*)d_in[3];
    const float* bq  = (const float*)d_in[4];
    const float* Wk  = (const float*)d_in[5];
    const float* bk  = (const float*)d_in[6];
    const float* Wv  = (const float*)d_in[7];
    const float* bv  = (const float*)d_in[8];
    const float* Wo  = (const float*)d_in[9];
    const float* bo  = (const float*)d_in[10];
    const int*   mask = (const int*)d_in[11];
    float* out = (float*)d_out;

    conv3x3_kernel<<<dim3(16, 8, 24), 256>>>(q, k, v, Wq, Wk, Wv, bq, bk, bv);
    attn_kernel<<<dim3(16, 16, 8), 256>>>(mask);
    proj_kernel<<<dim3(16, 128), 256>>>(Wo, bo, out);
}

// round 9
// speedup vs baseline: 3.6881x; 3.6881x over previous
#include <cuda_runtime.h>
#include <cuda_bf16.h>
#include <cstdint>
#include <math.h>

#define DIMC 1024
#define BATCH 8
#define NHEADS 16
#define HDIM 64

// ---------------------------------------------------------------------------
// Scratch (static device arrays: allocation-free rule)
// ---------------------------------------------------------------------------
__device__ float g_qc[BATCH * DIMC * DIMC];
__device__ float g_kc[BATCH * DIMC * DIMC];
__device__ float g_vc[BATCH * DIMC * DIMC];
__device__ float g_ao[BATCH * DIMC * DIMC];

// bf16-split weight matrices, layout [conv][o][k'] with k' = t*1024 + ic
__device__ __nv_bfloat16 g_Wh[3ULL * 1024 * 9216];
__device__ __nv_bfloat16 g_Wl[3ULL * 1024 * 9216];
// bf16-split im2col inputs, layout [conv*8+b][p][k']
__device__ __nv_bfloat16 g_Bh[24ULL * 1024 * 9216];
__device__ __nv_bfloat16 g_Bl[24ULL * 1024 * 9216];

// ---------------------------------------------------------------------------
// Helpers (portable sm_80+ PTX only — tcgen05 is rejected by this build's
// ptxas target sm_103 [no 'a'], so we use ldmatrix + mma.sync HMMA path)
// ---------------------------------------------------------------------------
__device__ __forceinline__ uint32_t smem_u32(const void* p) {
    uint32_t a;
    asm("{ .reg .u64 t; cvta.to.shared.u64 t, %1; cvt.u32.u64 %0, t; }" : "=r"(a) : "l"(p));
    return a;
}

#define SWZ128(off) ((off) ^ (((off) >> 3) & 0x70))

__device__ __forceinline__ void ldsm_x4(uint32_t &r0, uint32_t &r1, uint32_t &r2, uint32_t &r3,
                                        uint32_t addr) {
    asm volatile("ldmatrix.sync.aligned.m8n8.x4.shared.b16 {%0,%1,%2,%3}, [%4];"
                 : "=r"(r0), "=r"(r1), "=r"(r2), "=r"(r3) : "r"(addr));
}
__device__ __forceinline__ void ldsm_x2(uint32_t &r0, uint32_t &r1, uint32_t addr) {
    asm volatile("ldmatrix.sync.aligned.m8n8.x2.shared.b16 {%0,%1}, [%2];"
                 : "=r"(r0), "=r"(r1) : "r"(addr));
}
__device__ __forceinline__ void mma16816(float &c0, float &c1, float &c2, float &c3,
                                         uint32_t a0, uint32_t a1, uint32_t a2, uint32_t a3,
                                         uint32_t b0, uint32_t b1) {
    asm volatile("mma.sync.aligned.m16n8k16.row.col.f32.bf16.bf16.f32 "
                 "{%0,%1,%2,%3}, {%4,%5,%6,%7}, {%8,%9}, {%0,%1,%2,%3};"
                 : "+f"(c0), "+f"(c1), "+f"(c2), "+f"(c3)
                 : "r"(a0), "r"(a1), "r"(a2), "r"(a3), "r"(b0), "r"(b1));
}

// ---------------------------------------------------------------------------
// prep_a: W[o][ic*9+t] f32 -> g_Wh/g_Wl [conv][o][t*1024+ic] bf16 (hi/lo split)
// grid (1024 o, 3 conv), 256 threads
// ---------------------------------------------------------------------------
__global__ __launch_bounds__(256) void prep_a_kernel(
    const float* __restrict__ Wq, const float* __restrict__ Wk, const float* __restrict__ Wv)
{
    __shared__ float row[9216];
    const int conv = blockIdx.y, o = blockIdx.x, tid = threadIdx.x;
    const float* w = (conv == 0) ? Wq : (conv == 1) ? Wk : Wv;
    const float* src = w + (size_t)o * 9216;
    for (int i = tid; i < 9216; i += 256) row[i] = src[i];
    __syncthreads();

    __nv_bfloat16* dh = g_Wh + ((size_t)conv * 1024 + o) * 9216;
    __nv_bfloat16* dl = g_Wl + ((size_t)conv * 1024 + o) * 9216;
    for (int g = tid; g < 1152; g += 256) {   // 9 taps * 128 ic-chunks of 8
        int t = g >> 7;
        int icb = (g & 127) * 8;
        unsigned int hw[4], lw[4];
#pragma unroll
        for (int pr = 0; pr < 4; pr++) {
            unsigned short hs0, hs1, ls0, ls1;
#pragma unroll
            for (int q = 0; q < 2; q++) {
                float v = row[(icb + pr * 2 + q) * 9 + t];
                __nv_bfloat16 h = __float2bfloat16(v);
                float hv = __bfloat162float(h);
                __nv_bfloat16 l = __float2bfloat16(v - hv);
                if (q == 0) { hs0 = __bfloat16_as_ushort(h); ls0 = __bfloat16_as_ushort(l); }
                else        { hs1 = __bfloat16_as_ushort(h); ls1 = __bfloat16_as_ushort(l); }
            }
            hw[pr] = (unsigned)hs0 | ((unsigned)hs1 << 16);
            lw[pr] = (unsigned)ls0 | ((unsigned)ls1 << 16);
        }
        uint4 hv4 = {hw[0], hw[1], hw[2], hw[3]};
        uint4 lv4 = {lw[0], lw[1], lw[2], lw[3]};
        *(uint4*)(dh + (size_t)t * 1024 + icb) = hv4;
        *(uint4*)(dl + (size_t)t * 1024 + icb) = lv4;
    }
}

// ---------------------------------------------------------------------------
// prep_b: im2col + bf16 hi/lo split.
// B[p][t*1024+ic] = X[ic][y+r-1][x+c-1] (zero OOB), p = y*32+x, t = r*3+c.
// grid (128 ic-chunks of 8, 24 conv*batch), 256 threads. smem 32KB.
// ---------------------------------------------------------------------------
__global__ __launch_bounds__(256) void prep_b_kernel(
    const float* __restrict__ q, const float* __restrict__ k, const float* __restrict__ v)
{
    __shared__ float Xs[8 * 1024];
    const int cb = blockIdx.y;
    const int ic0 = blockIdx.x * 8;
    const int conv = cb >> 3, b = cb & 7;
    const float* src = ((conv == 0) ? q : (conv == 1) ? k : v) + ((size_t)b * 1024 + ic0) * 1024;
    for (int i = threadIdx.x; i < 8192; i += 256) Xs[i] = src[i];
    __syncthreads();

    __nv_bfloat16* bh = g_Bh + (size_t)cb * 1024 * 9216;
    __nv_bfloat16* bl = g_Bl + (size_t)cb * 1024 * 9216;
    for (int e = threadIdx.x; e < 9216; e += 256) {
        int t = e >> 10;                  // 0..8
        int p = e & 1023;
        int y = p >> 5, x = p & 31;
        int r = t / 3, c = t - r * 3;
        int sy = y + r - 1, sx = x + c - 1;
        bool ok = ((unsigned)sy < 32u) && ((unsigned)sx < 32u);
        int so = sy * 32 + sx;
        unsigned int hw[4], lw[4];
#pragma unroll
        for (int pr = 0; pr < 4; pr++) {
            unsigned short hs0, hs1, ls0, ls1;
#pragma unroll
            for (int qq = 0; qq < 2; qq++) {
                int i = pr * 2 + qq;
                float vv = ok ? Xs[i * 1024 + so] : 0.f;
                __nv_bfloat16 h = __float2bfloat16(vv);
                float hv = __bfloat162float(h);
                __nv_bfloat16 l = __float2bfloat16(vv - hv);
                if (qq == 0) { hs0 = __bfloat16_as_ushort(h); ls0 = __bfloat16_as_ushort(l); }
                else         { hs1 = __bfloat16_as_ushort(h); ls1 = __bfloat16_as_ushort(l); }
            }
            hw[pr] = (unsigned)hs0 | ((unsigned)hs1 << 16);
            lw[pr] = (unsigned)ls0 | ((unsigned)ls1 << 16);
        }
        size_t off = (size_t)p * 9216 + t * 1024 + ic0;
        uint4 hv4 = {hw[0], hw[1], hw[2], hw[3]};
        uint4 lv4 = {lw[0], lw[1], lw[2], lw[3]};
        *(uint4*)(bh + off) = hv4;
        *(uint4*)(bl + off) = lv4;
    }
}

// ---------------------------------------------------------------------------
// conv GEMM via mma.sync (HMMA bf16, 3-term hi/lo split):
// C[o][p] = sum_k' (Ah+Al)[o][k'] * (Bh+Bl)[p][k'] + bias[o]
// Tile 128x128 per CTA, K-slice 64, double-buffered cp.async, SW128 swizzle.
// 8 warps: warp grid 2(M) x 4(N), warp tile 64x32 = 4x4 m16n8k16.
// grid (8 p-tiles, 8 o-tiles, 24 conv*batch), 256 threads, 129KB dyn smem.
// ---------------------------------------------------------------------------
#define GEMM_SMEM_BYTES (131072 + 1024)
#define NSLICES 144

__global__ __launch_bounds__(256, 1) void conv_gemm_kernel(
    const float* __restrict__ bq, const float* __restrict__ bk, const float* __restrict__ bv)
{
    extern __shared__ char dynsmem[];
    const uint32_t raw = smem_u32(dynsmem);
    const uint32_t base = (raw + 1023u) & ~1023u;  // 2 bufs x 4 mats x 16KB

    const int tid = threadIdx.x;
    const int wid = tid >> 5, lane = tid & 31;
    const int p0 = blockIdx.x * 128;
    const int o0 = blockIdx.y * 128;
    const int cb = blockIdx.z;
    const int conv = cb >> 3, b = cb & 7;

    const int wm = wid & 1;          // 0..1 : M group of 64
    const int wn = wid >> 1;         // 0..3 : N group of 32

    const __nv_bfloat16* bases[4] = {
        g_Wh + ((size_t)conv * 1024 + o0) * 9216,
        g_Wl + ((size_t)conv * 1024 + o0) * 9216,
        g_Bh + ((size_t)cb * 1024 + p0) * 9216,
        g_Bl + ((size_t)cb * 1024 + p0) * 9216,
    };

    auto fill = [&](int bsel, int k0) {
#pragma unroll
        for (int j = 0; j < 16; j++) {
            const int sub = j >> 2;                 // 0:Ah 1:Al 2:Bh 3:Bl
            int qq = tid + 256 * (j & 3);           // 0..1023 in sub-buffer
            int r = qq >> 3, c16 = qq & 7;          // row 0..127, 16B chunk
            uint32_t off = (uint32_t)(r * 128 + c16 * 16);
            uint32_t dst = base + (uint32_t)bsel * 65536u + (uint32_t)sub * 16384u + SWZ128(off);
            const void* src = (const void*)(bases[sub] + (size_t)r * 9216 + k0 + c16 * 8);
            asm volatile("cp.async.cg.shared.global [%0], [%1], 16;" :: "r"(dst), "l"(src));
        }
        asm volatile("cp.async.commit_group;");
    };

    float acc[4][4][4];
#pragma unroll
    for (int i = 0; i < 4; i++)
#pragma unroll
        for (int j = 0; j < 4; j++)
#pragma unroll
            for (int e = 0; e < 4; e++) acc[i][j][e] = 0.f;

    // Per-lane ldmatrix address components
    const int a_r  = lane & 15;             // A: row within 16
    const int a_c8 = (lane >> 4) * 8;       // A: k-col 0 or 8
    const int b_r  = lane & 7;              // B: row within 8
    const int b_c8 = ((lane >> 3) & 1) * 8; // B: k-col 0 or 8

    fill(0, 0);

    for (int s = 0; s < NSLICES; s++) {
        const int bsel = s & 1;
        if (s + 1 < NSLICES) {
            fill(bsel ^ 1, (s + 1) * 64);
            asm volatile("cp.async.wait_group 1;");
        } else {
            asm volatile("cp.async.wait_group 0;");
        }
        __syncthreads();

        const uint32_t bb   = base + (uint32_t)bsel * 65536u;
        const uint32_t bAh  = bb;
        const uint32_t bAl  = bb + 16384u;
        const uint32_t bBh  = bb + 32768u;
        const uint32_t bBl  = bb + 49152u;

#pragma unroll
        for (int kc = 0; kc < 64; kc += 16) {
            uint32_t ah[4][4], al[4][4];
#pragma unroll
            for (int i = 0; i < 4; i++) {
                uint32_t off = (uint32_t)((wm * 64 + i * 16 + a_r) * 128 + (kc + a_c8) * 2);
                uint32_t sw = SWZ128(off);
                ldsm_x4(ah[i][0], ah[i][1], ah[i][2], ah[i][3], bAh + sw);
                ldsm_x4(al[i][0], al[i][1], al[i][2], al[i][3], bAl + sw);
            }
            uint32_t bh[4][2], bl[4][2];
#pragma unroll
            for (int j = 0; j < 4; j++) {
                uint32_t off = (uint32_t)((wn * 32 + j * 8 + b_r) * 128 + (kc + b_c8) * 2);
                uint32_t sw = SWZ128(off);
                ldsm_x2(bh[j][0], bh[j][1], bBh + sw);
                ldsm_x2(bl[j][0], bl[j][1], bBl + sw);
            }
#pragma unroll
            for (int i = 0; i < 4; i++)
#pragma unroll
                for (int j = 0; j < 4; j++) {
                    mma16816(acc[i][j][0], acc[i][j][1], acc[i][j][2], acc[i][j][3],
                             ah[i][0], ah[i][1], ah[i][2], ah[i][3], bh[j][0], bh[j][1]);
                    mma16816(acc[i][j][0], acc[i][j][1], acc[i][j][2], acc[i][j][3],
                             ah[i][0], ah[i][1], ah[i][2], ah[i][3], bl[j][0], bl[j][1]);
                    mma16816(acc[i][j][0], acc[i][j][1], acc[i][j][2], acc[i][j][3],
                             al[i][0], al[i][1], al[i][2], al[i][3], bh[j][0], bh[j][1]);
                }
        }
        __syncthreads();   // all warps done reading before next fill overwrites
    }

    // Epilogue: c-frag m16n8 layout: (row=lane>>2, col=2*(lane&3)) and row+8
    float* outp = ((conv == 0) ? g_qc : (conv == 1) ? g_kc : g_vc) + (size_t)b * (DIMC * DIMC);
    const float* bias = (conv == 0) ? bq : (conv == 1) ? bk : bv;
    const int cr = lane >> 2;
    const int cc = (lane & 3) * 2;
#pragma unroll
    for (int i = 0; i < 4; i++) {
        const int o_lo = o0 + wm * 64 + i * 16 + cr;
        const int o_hi = o_lo + 8;
        const float bb0 = bias[o_lo];
        const float bb1 = bias[o_hi];
#pragma unroll
        for (int j = 0; j < 4; j++) {
            const int p = p0 + wn * 32 + j * 8 + cc;
            float2 v0 = {acc[i][j][0] + bb0, acc[i][j][1] + bb0};
            float2 v1 = {acc[i][j][2] + bb1, acc[i][j][3] + bb1};
            *(float2*)(outp + (size_t)o_lo * 1024 + p) = v0;
            *(float2*)(outp + (size_t)o_hi * 1024 + p) = v1;
        }
    }
}

// ---------------------------------------------------------------------------
// Flash-style attention (unchanged from passing R4 kernel)
// ---------------------------------------------------------------------------
__global__ __launch_bounds__(256) void attn_kernel(const int* __restrict__ mask)
{
    __shared__ float Qs[64 * 64];
    __shared__ float KPs[64 * 64];
    __shared__ float Vs[64 * 64];

    const int tid = threadIdx.x;
    const int tx = tid & 15, ty = tid >> 4;
    const int t0 = blockIdx.x * 64;
    const int hd = blockIdx.y;
    const int b  = blockIdx.z;

    const float* Qg = g_qc + (size_t)b * DIMC * DIMC + hd * HDIM;
    const float* Kg = g_kc + (size_t)b * DIMC * DIMC + hd * HDIM;
    const float* Vg = g_vc + (size_t)b * DIMC * DIMC + hd * HDIM;
    const int* mrow = mask + (size_t)b * DIMC * DIMC;

    for (int idx = tid; idx < 4096; idx += 256) {
        int t = idx >> 6, d = idx & 63;
        Qs[t * 64 + ((d + t) & 63)] = Qg[(size_t)(t0 + t) * 1024 + d];
    }

    float m[4], l[4], acc[4][4];
#pragma unroll
    for (int a = 0; a < 4; a++) {
        m[a] = -INFINITY; l[a] = 0.f;
#pragma unroll
        for (int u = 0; u < 4; u++) acc[a][u] = 0.f;
    }

    const float scale = 0.125f;

    for (int s0 = 0; s0 < 1024; s0 += 64) {
        __syncthreads();
#pragma unroll
        for (int rep = 0; rep < 4; rep++) {
            int idx = tid + 256 * rep;
            int s   = idx >> 4;
            int k4  = (idx & 15) * 4;
            const float4 kv = *(const float4*)(Kg + (size_t)(s0 + s) * 1024 + k4);
            KPs[(k4 + 0) * 64 + ((s + k4 + 0) & 63)] = kv.x;
            KPs[(k4 + 1) * 64 + ((s + k4 + 1) & 63)] = kv.y;
            KPs[(k4 + 2) * 64 + ((s + k4 + 2) & 63)] = kv.z;
            KPs[(k4 + 3) * 64 + ((s + k4 + 3) & 63)] = kv.w;
        }
#pragma unroll
        for (int rep = 0; rep < 4; rep++) {
            int idx = tid + 256 * rep;
            int s   = idx >> 4;
            int d4  = (idx & 15) * 4;
            const float4 vv = *(const float4*)(Vg + (size_t)(s0 + s) * 1024 + d4);
            *(float4*)(Vs + s * 64 + d4) = vv;
        }
        __syncthreads();

        float sv[4][4];
#pragma unroll
        for (int a = 0; a < 4; a++)
#pragma unroll
            for (int bb = 0; bb < 4; bb++) sv[a][bb] = 0.f;

#pragma unroll 8
        for (int k = 0; k < 64; k++) {
            float qr[4], kr[4];
#pragma unroll
            for (int a = 0; a < 4; a++) {
                int tr = ty + 16 * a;
                qr[a] = Qs[tr * 64 + ((k + tr) & 63)];
            }
#pragma unroll
            for (int bb = 0; bb < 4; bb++) {
                int sc = tx + 16 * bb;
                kr[bb] = KPs[k * 64 + ((sc + k) & 63)];
            }
#pragma unroll
            for (int a = 0; a < 4; a++)
#pragma unroll
                for (int bb = 0; bb < 4; bb++) sv[a][bb] += qr[a] * kr[bb];
        }

#pragma unroll
        for (int a = 0; a < 4; a++) {
            int t = t0 + ty + 16 * a;
#pragma unroll
            for (int bb = 0; bb < 4; bb++) {
                int s = s0 + tx + 16 * bb;
                int mv = mrow[(size_t)t * 1024 + s];
                sv[a][bb] = (mv == 0) ? -1e9f : sv[a][bb] * scale;
            }
        }
        __syncthreads();

#pragma unroll
        for (int a = 0; a < 4; a++) {
            float rm = fmaxf(fmaxf(sv[a][0], sv[a][1]), fmaxf(sv[a][2], sv[a][3]));
            rm = fmaxf(rm, __shfl_xor_sync(0xffffffffu, rm, 1));
            rm = fmaxf(rm, __shfl_xor_sync(0xffffffffu, rm, 2));
            rm = fmaxf(rm, __shfl_xor_sync(0xffffffffu, rm, 4));
            rm = fmaxf(rm, __shfl_xor_sync(0xffffffffu, rm, 8));
            float mnew = fmaxf(m[a], rm);
            float fac = __expf(m[a] - mnew);
            float rsum = 0.f;
#pragma unroll
            for (int bb = 0; bb < 4; bb++) {
                float p = __expf(sv[a][bb] - mnew);
                sv[a][bb] = p;
                rsum += p;
            }
            rsum += __shfl_xor_sync(0xffffffffu, rsum, 1);
            rsum += __shfl_xor_sync(0xffffffffu, rsum, 2);
            rsum += __shfl_xor_sync(0xffffffffu, rsum, 4);
            rsum += __shfl_xor_sync(0xffffffffu, rsum, 8);
            l[a] = l[a] * fac + rsum;
            m[a] = mnew;
#pragma unroll
            for (int u = 0; u < 4; u++) acc[a][u] *= fac;
            int tr = ty + 16 * a;
#pragma unroll
            for (int bb = 0; bb < 4; bb++) {
                int sc = tx + 16 * bb;
                KPs[tr * 64 + ((sc + tr) & 63)] = sv[a][bb];
            }
        }
        __syncthreads();

#pragma unroll 8
        for (int s = 0; s < 64; s++) {
            float pr[4], vr[4];
#pragma unroll
            for (int a = 0; a < 4; a++) {
                int tr = ty + 16 * a;
                pr[a] = KPs[tr * 64 + ((s + tr) & 63)];
            }
#pragma unroll
            for (int u = 0; u < 4; u++) vr[u] = Vs[s * 64 + tx + 16 * u];
#pragma unroll
            for (int a = 0; a < 4; a++)
#pragma unroll
                for (int u = 0; u < 4; u++) acc[a][u] += pr[a] * vr[u];
        }
    }

    float* og = g_ao + (size_t)b * DIMC * DIMC + hd * HDIM;
#pragma unroll
    for (int a = 0; a < 4; a++) {
        float inv = 1.f / l[a];
        int t = t0 + ty + 16 * a;
#pragma unroll
        for (int u = 0; u < 4; u++)
            og[(size_t)t * 1024 + tx + 16 * u] = acc[a][u] * inv;
    }
}

// ---------------------------------------------------------------------------
// Output projection (unchanged from passing R4 kernel)
// ---------------------------------------------------------------------------
__global__ __launch_bounds__(256) void proj_kernel(
    const float* __restrict__ Wo, const float* __restrict__ bo, float* __restrict__ out)
{
    __shared__ float As[64 * 17];
    __shared__ float Bs[16 * 64];

    const int tid = threadIdx.x;
    const int tx = tid & 15, ty = tid >> 4;
    const int j0 = blockIdx.x * 64;
    const int m0 = blockIdx.y * 64;

    float acc[4][4];
#pragma unroll
    for (int a = 0; a < 4; a++)
#pragma unroll
        for (int u = 0; u < 4; u++) acc[a][u] = 0.f;

    const float* A = g_ao;
    for (int c0 = 0; c0 < 1024; c0 += 16) {
        for (int idx = tid; idx < 1024; idx += 256) {
            int mm = idx >> 4, c = idx & 15;
            As[mm * 17 + c] = A[(size_t)(m0 + mm) * 1024 + c0 + c];
        }
        {
            int j = tid >> 2;
            int cq = (tid & 3) * 4;
            const float4 wv = *(const float4*)(Wo + (size_t)(j0 + j) * 1024 + c0 + cq);
            Bs[(cq + 0) * 64 + j] = wv.x;
            Bs[(cq + 1) * 64 + j] = wv.y;
            Bs[(cq + 2) * 64 + j] = wv.z;
            Bs[(cq + 3) * 64 + j] = wv.w;
        }
        __syncthreads();
#pragma unroll
        for (int c = 0; c < 16; c++) {
            float ar[4], br[4];
#pragma unroll
            for (int a = 0; a < 4; a++) ar[a] = As[(ty + 16 * a) * 17 + c];
#pragma unroll
            for (int u = 0; u < 4; u++) br[u] = Bs[c * 64 + tx + 16 * u];
#pragma unroll
            for (int a = 0; a < 4; a++)
#pragma unroll
                for (int u = 0; u < 4; u++) acc[a][u] += ar[a] * br[u];
        }
        __syncthreads();
    }

#pragma unroll
    for (int a = 0; a < 4; a++) {
        int row = m0 + ty + 16 * a;
#pragma unroll
        for (int u = 0; u < 4; u++) {
            int j = j0 + tx + 16 * u;
            out[(size_t)row * 1024 + j] = acc[a][u] + bo[j];
        }
    }
}

// ---------------------------------------------------------------------------
extern "C" void kernel_launch(void* const* d_in, const int* in_sizes, int n_in,
                              void* d_out, int out_size)
{
    const float* q   = (const float*)d_in[0];
    const float* k   = (const float*)d_in[1];
    const float* v   = (const float*)d_in[2];
    const float* Wq  = (const float*)d_in[3];
    const float* bq  = (const float*)d_in[4];
    const float* Wk  = (const float*)d_in[5];
    const float* bk  = (const float*)d_in[6];
    const float* Wv  = (const float*)d_in[7];
    const float* bv  = (const float*)d_in[8];
    const float* Wo  = (const float*)d_in[9];
    const float* bo  = (const float*)d_in[10];
    const int*   mask = (const int*)d_in[11];
    float* out = (float*)d_out;

    cudaFuncSetAttribute(conv_gemm_kernel,
                         cudaFuncAttributeMaxDynamicSharedMemorySize, GEMM_SMEM_BYTES);

    prep_a_kernel<<<dim3(1024, 3), 256>>>(Wq, Wk, Wv);
    prep_b_kernel<<<dim3(128, 24), 256>>>(q, k, v);
    conv_gemm_kernel<<<dim3(8, 8, 24), 256, GEMM_SMEM_BYTES>>>(bq, bk, bv);
    attn_kernel<<<dim3(16, 16, 8), 256>>>(mask);
    proj_kernel<<<dim3(16, 128), 256>>>(Wo, bo, out);
}

// round 10
// speedup vs baseline: 7.1806x; 1.9469x over previous
#include <cuda_runtime.h>
#include <cuda_fp16.h>
#include <cstdint>
#include <math.h>

#define DIMC 1024
#define BATCH 8
#define NHEADS 16
#define HDIM 64

// ---------------------------------------------------------------------------
// Scratch (static device arrays: allocation-free rule)
// ---------------------------------------------------------------------------
__device__ float g_qc[BATCH * DIMC * DIMC];
__device__ float g_kc[BATCH * DIMC * DIMC];
__device__ float g_vc[BATCH * DIMC * DIMC];
__device__ float g_ao[BATCH * DIMC * DIMC];

// fp16 weight matrices, layout [conv][o][k'] with k' = t*1024 + ic
__device__ __half g_W16[3ULL * 1024 * 9216];
// fp16 im2col inputs, layout [conv*8+b][p][k']
__device__ __half g_B16[24ULL * 1024 * 9216];

// ---------------------------------------------------------------------------
// Helpers (portable sm_80+ PTX only — tcgen05 rejected by this build's ptxas
// target sm_103 [no 'a']; ldmatrix + mma.sync HMMA path instead)
// ---------------------------------------------------------------------------
__device__ __forceinline__ uint32_t smem_u32(const void* p) {
    uint32_t a;
    asm("{ .reg .u64 t; cvta.to.shared.u64 t, %1; cvt.u32.u64 %0, t; }" : "=r"(a) : "l"(p));
    return a;
}

#define SWZ128(off) ((off) ^ (((off) >> 3) & 0x70))

__device__ __forceinline__ void ldsm_x4(uint32_t &r0, uint32_t &r1, uint32_t &r2, uint32_t &r3,
                                        uint32_t addr) {
    asm volatile("ldmatrix.sync.aligned.m8n8.x4.shared.b16 {%0,%1,%2,%3}, [%4];"
                 : "=r"(r0), "=r"(r1), "=r"(r2), "=r"(r3) : "r"(addr));
}
__device__ __forceinline__ void ldsm_x2(uint32_t &r0, uint32_t &r1, uint32_t addr) {
    asm volatile("ldmatrix.sync.aligned.m8n8.x2.shared.b16 {%0,%1}, [%2];"
                 : "=r"(r0), "=r"(r1) : "r"(addr));
}
__device__ __forceinline__ void mma16816_f16(float &c0, float &c1, float &c2, float &c3,
                                             uint32_t a0, uint32_t a1, uint32_t a2, uint32_t a3,
                                             uint32_t b0, uint32_t b1) {
    asm volatile("mma.sync.aligned.m16n8k16.row.col.f32.f16.f16.f32 "
                 "{%0,%1,%2,%3}, {%4,%5,%6,%7}, {%8,%9}, {%0,%1,%2,%3};"
                 : "+f"(c0), "+f"(c1), "+f"(c2), "+f"(c3)
                 : "r"(a0), "r"(a1), "r"(a2), "r"(a3), "r"(b0), "r"(b1));
}

// ---------------------------------------------------------------------------
// prep_a: W[o][ic*9+t] f32 -> g_W16 [conv][o][t*1024+ic] fp16
// grid (1024 o, 3 conv), 256 threads
// ---------------------------------------------------------------------------
__global__ __launch_bounds__(256) void prep_a_kernel(
    const float* __restrict__ Wq, const float* __restrict__ Wk, const float* __restrict__ Wv)
{
    __shared__ float row[9216];
    const int conv = blockIdx.y, o = blockIdx.x, tid = threadIdx.x;
    const float* w = (conv == 0) ? Wq : (conv == 1) ? Wk : Wv;
    const float* src = w + (size_t)o * 9216;
    for (int i = tid; i < 9216; i += 256) row[i] = src[i];
    __syncthreads();

    __half* dh = g_W16 + ((size_t)conv * 1024 + o) * 9216;
    for (int g = tid; g < 1152; g += 256) {   // 9 taps * 128 ic-chunks of 8
        int t = g >> 7;
        int icb = (g & 127) * 8;
        unsigned int hw[4];
#pragma unroll
        for (int pr = 0; pr < 4; pr++) {
            __half h0 = __float2half_rn(row[(icb + pr * 2 + 0) * 9 + t]);
            __half h1 = __float2half_rn(row[(icb + pr * 2 + 1) * 9 + t]);
            hw[pr] = (unsigned)__half_as_ushort(h0) | ((unsigned)__half_as_ushort(h1) << 16);
        }
        uint4 hv4 = {hw[0], hw[1], hw[2], hw[3]};
        *(uint4*)(dh + (size_t)t * 1024 + icb) = hv4;
    }
}

// ---------------------------------------------------------------------------
// prep_b: im2col + fp16 convert.
// B[p][t*1024+ic] = X[ic][y+r-1][x+c-1] (zero OOB), p = y*32+x, t = r*3+c.
// grid (128 ic-chunks of 8, 24 conv*batch), 256 threads. smem 32KB.
// ---------------------------------------------------------------------------
__global__ __launch_bounds__(256) void prep_b_kernel(
    const float* __restrict__ q, const float* __restrict__ k, const float* __restrict__ v)
{
    __shared__ float Xs[8 * 1024];
    const int cb = blockIdx.y;
    const int ic0 = blockIdx.x * 8;
    const int conv = cb >> 3, b = cb & 7;
    const float* src = ((conv == 0) ? q : (conv == 1) ? k : v) + ((size_t)b * 1024 + ic0) * 1024;
    for (int i = threadIdx.x; i < 8192; i += 256) Xs[i] = src[i];
    __syncthreads();

    __half* bh = g_B16 + (size_t)cb * 1024 * 9216;
    for (int e = threadIdx.x; e < 9216; e += 256) {
        int t = e >> 10;                  // 0..8
        int p = e & 1023;
        int y = p >> 5, x = p & 31;
        int r = t / 3, c = t - r * 3;
        int sy = y + r - 1, sx = x + c - 1;
        bool ok = ((unsigned)sy < 32u) && ((unsigned)sx < 32u);
        int so = sy * 32 + sx;
        unsigned int hw[4];
#pragma unroll
        for (int pr = 0; pr < 4; pr++) {
            float v0 = ok ? Xs[(pr * 2 + 0) * 1024 + so] : 0.f;
            float v1 = ok ? Xs[(pr * 2 + 1) * 1024 + so] : 0.f;
            __half h0 = __float2half_rn(v0);
            __half h1 = __float2half_rn(v1);
            hw[pr] = (unsigned)__half_as_ushort(h0) | ((unsigned)__half_as_ushort(h1) << 16);
        }
        uint4 hv4 = {hw[0], hw[1], hw[2], hw[3]};
        *(uint4*)(bh + (size_t)p * 9216 + t * 1024 + ic0) = hv4;
    }
}

// ---------------------------------------------------------------------------
// conv GEMM via mma.sync (HMMA fp16, single term):
// C[o][p] = sum_k' W16[o][k'] * B16[p][k'] + bias[o]
// Tile 128x128 per CTA, K-slice 64, double-buffered cp.async, SW128 swizzle.
// 8 warps: warp grid 2(M) x 4(N), warp tile 64x32 = 4x4 m16n8k16.
// grid (8 p-tiles, 8 o-tiles, 24 conv*batch), 256 threads, 66KB dyn smem.
// ---------------------------------------------------------------------------
#define GEMM_SMEM_BYTES (65536 + 1024)
#define NSLICES 144

__global__ __launch_bounds__(256, 2) void conv_gemm_kernel(
    const float* __restrict__ bq, const float* __restrict__ bk, const float* __restrict__ bv)
{
    extern __shared__ char dynsmem[];
    const uint32_t raw = smem_u32(dynsmem);
    const uint32_t base = (raw + 1023u) & ~1023u;  // 2 bufs x 2 mats x 16KB

    const int tid = threadIdx.x;
    const int wid = tid >> 5, lane = tid & 31;
    const int p0 = blockIdx.x * 128;
    const int o0 = blockIdx.y * 128;
    const int cb = blockIdx.z;
    const int conv = cb >> 3, b = cb & 7;

    const int wm = wid & 1;          // 0..1 : M group of 64
    const int wn = wid >> 1;         // 0..3 : N group of 32

    const __half* baseA = g_W16 + ((size_t)conv * 1024 + o0) * 9216;
    const __half* baseB = g_B16 + ((size_t)cb * 1024 + p0) * 9216;

    auto fill = [&](int bsel, int k0) {
#pragma unroll
        for (int j = 0; j < 8; j++) {
            const int sub = j >> 2;                 // 0:A 1:B
            int qq = tid + 256 * (j & 3);           // 0..1023 in sub-buffer
            int r = qq >> 3, c16 = qq & 7;          // row 0..127, 16B chunk
            uint32_t off = (uint32_t)(r * 128 + c16 * 16);
            uint32_t dst = base + (uint32_t)bsel * 32768u + (uint32_t)sub * 16384u + SWZ128(off);
            const __half* srcb = (sub == 0) ? baseA : baseB;
            const void* src = (const void*)(srcb + (size_t)r * 9216 + k0 + c16 * 8);
            asm volatile("cp.async.cg.shared.global [%0], [%1], 16;" :: "r"(dst), "l"(src));
        }
        asm volatile("cp.async.commit_group;");
    };

    float acc[4][4][4];
#pragma unroll
    for (int i = 0; i < 4; i++)
#pragma unroll
        for (int j = 0; j < 4; j++)
#pragma unroll
            for (int e = 0; e < 4; e++) acc[i][j][e] = 0.f;

    const int a_r  = lane & 15;             // A: row within 16
    const int a_c8 = (lane >> 4) * 8;       // A: k-col 0 or 8
    const int b_r  = lane & 7;              // B: row within 8
    const int b_c8 = ((lane >> 3) & 1) * 8; // B: k-col 0 or 8

    fill(0, 0);

    for (int s = 0; s < NSLICES; s++) {
        const int bsel = s & 1;
        if (s + 1 < NSLICES) {
            fill(bsel ^ 1, (s + 1) * 64);
            asm volatile("cp.async.wait_group 1;");
        } else {
            asm volatile("cp.async.wait_group 0;");
        }
        __syncthreads();

        const uint32_t bb = base + (uint32_t)bsel * 32768u;
        const uint32_t bA = bb;
        const uint32_t bB = bb + 16384u;

#pragma unroll
        for (int kc = 0; kc < 64; kc += 16) {
            uint32_t ah[4][4];
#pragma unroll
            for (int i = 0; i < 4; i++) {
                uint32_t off = (uint32_t)((wm * 64 + i * 16 + a_r) * 128 + (kc + a_c8) * 2);
                uint32_t sw = SWZ128(off);
                ldsm_x4(ah[i][0], ah[i][1], ah[i][2], ah[i][3], bA + sw);
            }
            uint32_t bh[4][2];
#pragma unroll
            for (int j = 0; j < 4; j++) {
                uint32_t off = (uint32_t)((wn * 32 + j * 8 + b_r) * 128 + (kc + b_c8) * 2);
                uint32_t sw = SWZ128(off);
                ldsm_x2(bh[j][0], bh[j][1], bB + sw);
            }
#pragma unroll
            for (int i = 0; i < 4; i++)
#pragma unroll
                for (int j = 0; j < 4; j++)
                    mma16816_f16(acc[i][j][0], acc[i][j][1], acc[i][j][2], acc[i][j][3],
                                 ah[i][0], ah[i][1], ah[i][2], ah[i][3], bh[j][0], bh[j][1]);
        }
        __syncthreads();   // all warps done reading before next fill overwrites
    }

    // Epilogue: c-frag m16n8: (row=lane>>2, col=2*(lane&3)) and row+8
    float* outp = ((conv == 0) ? g_qc : (conv == 1) ? g_kc : g_vc) + (size_t)b * (DIMC * DIMC);
    const float* bias = (conv == 0) ? bq : (conv == 1) ? bk : bv;
    const int cr = lane >> 2;
    const int cc = (lane & 3) * 2;
#pragma unroll
    for (int i = 0; i < 4; i++) {
        const int o_lo = o0 + wm * 64 + i * 16 + cr;
        const int o_hi = o_lo + 8;
        const float bb0 = bias[o_lo];
        const float bb1 = bias[o_hi];
#pragma unroll
        for (int j = 0; j < 4; j++) {
            const int p = p0 + wn * 32 + j * 8 + cc;
            float2 v0 = {acc[i][j][0] + bb0, acc[i][j][1] + bb0};
            float2 v1 = {acc[i][j][2] + bb1, acc[i][j][3] + bb1};
            *(float2*)(outp + (size_t)o_lo * 1024 + p) = v0;
            *(float2*)(outp + (size_t)o_hi * 1024 + p) = v1;
        }
    }
}

// ---------------------------------------------------------------------------
// Flash-style attention, fp32 SIMT. Padded stride-65 smem (no rotation-swizzle
// index math). Dynamic smem: Qs[64*65] KPs[64*65] Vs[64*64] = 49664 B.
// grid (16 t-tiles, 16 heads, 8 batches), block 256 (16x16).
// ---------------------------------------------------------------------------
#define ATTN_SMEM_BYTES 49664

__global__ __launch_bounds__(256) void attn_kernel(const int* __restrict__ mask)
{
    extern __shared__ float smf[];
    float* Qs  = smf;                 // [t][d] stride 65
    float* KPs = smf + 64 * 65;       // K^T [k][s] stride 65; later P [t][s]
    float* Vs  = smf + 2 * 64 * 65;   // [s][d] stride 64

    const int tid = threadIdx.x;
    const int tx = tid & 15, ty = tid >> 4;
    const int t0 = blockIdx.x * 64;
    const int hd = blockIdx.y;
    const int b  = blockIdx.z;

    const float* Qg = g_qc + (size_t)b * DIMC * DIMC + hd * HDIM;
    const float* Kg = g_kc + (size_t)b * DIMC * DIMC + hd * HDIM;
    const float* Vg = g_vc + (size_t)b * DIMC * DIMC + hd * HDIM;
    const int* mrow = mask + (size_t)b * DIMC * DIMC;

    // Load Q tile [t][d] (padded rows: conflict-free)
#pragma unroll
    for (int rep = 0; rep < 4; rep++) {
        int idx = tid + 256 * rep;
        int t = idx >> 4;
        int d4 = (idx & 15) * 4;
        const float4 qv = *(const float4*)(Qg + (size_t)(t0 + t) * 1024 + d4);
        float* dst = Qs + t * 65 + d4;
        dst[0] = qv.x; dst[1] = qv.y; dst[2] = qv.z; dst[3] = qv.w;
    }

    float m[4], l[4], acc[4][4];
#pragma unroll
    for (int a = 0; a < 4; a++) {
        m[a] = -INFINITY; l[a] = 0.f;
#pragma unroll
        for (int u = 0; u < 4; u++) acc[a][u] = 0.f;
    }

    const float scale = 0.125f;  // 1/sqrt(64)

    for (int s0 = 0; s0 < 1024; s0 += 64) {
        __syncthreads();  // previous PV reads done before overwriting K/V/P
        // K transposed into KPs[k][s]; banks = (k4+i+s)%32 across lanes -> free
#pragma unroll
        for (int rep = 0; rep < 4; rep++) {
            int idx = tid + 256 * rep;
            int s   = idx >> 4;
            int k4  = (idx & 15) * 4;
            const float4 kv = *(const float4*)(Kg + (size_t)(s0 + s) * 1024 + k4);
            KPs[(k4 + 0) * 65 + s] = kv.x;
            KPs[(k4 + 1) * 65 + s] = kv.y;
            KPs[(k4 + 2) * 65 + s] = kv.z;
            KPs[(k4 + 3) * 65 + s] = kv.w;
        }
#pragma unroll
        for (int rep = 0; rep < 4; rep++) {
            int idx = tid + 256 * rep;
            int s   = idx >> 4;
            int d4  = (idx & 15) * 4;
            const float4 vv = *(const float4*)(Vg + (size_t)(s0 + s) * 1024 + d4);
            *(float4*)(Vs + s * 64 + d4) = vv;
        }
        __syncthreads();

        // S = Q K^T for this thread's 4x4 (t, s) micro-tile
        float sv[4][4];
#pragma unroll
        for (int a = 0; a < 4; a++)
#pragma unroll
            for (int bb = 0; bb < 4; bb++) sv[a][bb] = 0.f;

#pragma unroll 8
        for (int k = 0; k < 64; k++) {
            float qr[4], kr[4];
#pragma unroll
            for (int a = 0; a < 4; a++) qr[a] = Qs[(ty + 16 * a) * 65 + k];
#pragma unroll
            for (int bb = 0; bb < 4; bb++) kr[bb] = KPs[k * 65 + tx + 16 * bb];
#pragma unroll
            for (int a = 0; a < 4; a++)
#pragma unroll
                for (int bb = 0; bb < 4; bb++) sv[a][bb] += qr[a] * kr[bb];
        }

        // scale + mask (mask==0 -> -1e9, matching reference order)
#pragma unroll
        for (int a = 0; a < 4; a++) {
            int t = t0 + ty + 16 * a;
#pragma unroll
            for (int bb = 0; bb < 4; bb++) {
                int s = s0 + tx + 16 * bb;
                int mv = mrow[(size_t)t * 1024 + s];
                sv[a][bb] = (mv == 0) ? -1e9f : sv[a][bb] * scale;
            }
        }
        __syncthreads();  // all K reads complete before P overwrites KPs

        // Online softmax update + write P
#pragma unroll
        for (int a = 0; a < 4; a++) {
            float rm = fmaxf(fmaxf(sv[a][0], sv[a][1]), fmaxf(sv[a][2], sv[a][3]));
            rm = fmaxf(rm, __shfl_xor_sync(0xffffffffu, rm, 1));
            rm = fmaxf(rm, __shfl_xor_sync(0xffffffffu, rm, 2));
            rm = fmaxf(rm, __shfl_xor_sync(0xffffffffu, rm, 4));
            rm = fmaxf(rm, __shfl_xor_sync(0xffffffffu, rm, 8));
            float mnew = fmaxf(m[a], rm);
            float fac = __expf(m[a] - mnew);
            float rsum = 0.f;
#pragma unroll
            for (int bb = 0; bb < 4; bb++) {
                float p = __expf(sv[a][bb] - mnew);
                sv[a][bb] = p;
                rsum += p;
            }
            rsum += __shfl_xor_sync(0xffffffffu, rsum, 1);
            rsum += __shfl_xor_sync(0xffffffffu, rsum, 2);
            rsum += __shfl_xor_sync(0xffffffffu, rsum, 4);
            rsum += __shfl_xor_sync(0xffffffffu, rsum, 8);
            l[a] = l[a] * fac + rsum;
            m[a] = mnew;
#pragma unroll
            for (int u = 0; u < 4; u++) acc[a][u] *= fac;
            int tr = ty + 16 * a;
#pragma unroll
            for (int bb = 0; bb < 4; bb++)
                KPs[tr * 65 + tx + 16 * bb] = sv[a][bb];
        }
        __syncthreads();

        // O += P V
#pragma unroll 8
        for (int s = 0; s < 64; s++) {
            float pr[4], vr[4];
#pragma unroll
            for (int a = 0; a < 4; a++) pr[a] = KPs[(ty + 16 * a) * 65 + s];
#pragma unroll
            for (int u = 0; u < 4; u++) vr[u] = Vs[s * 64 + tx + 16 * u];
#pragma unroll
            for (int a = 0; a < 4; a++)
#pragma unroll
                for (int u = 0; u < 4; u++) acc[a][u] += pr[a] * vr[u];
        }
    }

    float* og = g_ao + (size_t)b * DIMC * DIMC + hd * HDIM;
#pragma unroll
    for (int a = 0; a < 4; a++) {
        float inv = 1.f / l[a];
        int t = t0 + ty + 16 * a;
#pragma unroll
        for (int u = 0; u < 4; u++)
            og[(size_t)t * 1024 + tx + 16 * u] = acc[a][u] * inv;
    }
}

// ---------------------------------------------------------------------------
// Output projection (unchanged)
// ---------------------------------------------------------------------------
__global__ __launch_bounds__(256) void proj_kernel(
    const float* __restrict__ Wo, const float* __restrict__ bo, float* __restrict__ out)
{
    __shared__ float As[64 * 17];
    __shared__ float Bs[16 * 64];

    const int tid = threadIdx.x;
    const int tx = tid & 15, ty = tid >> 4;
    const int j0 = blockIdx.x * 64;
    const int m0 = blockIdx.y * 64;

    float acc[4][4];
#pragma unroll
    for (int a = 0; a < 4; a++)
#pragma unroll
        for (int u = 0; u < 4; u++) acc[a][u] = 0.f;

    const float* A = g_ao;
    for (int c0 = 0; c0 < 1024; c0 += 16) {
        for (int idx = tid; idx < 1024; idx += 256) {
            int mm = idx >> 4, c = idx & 15;
            As[mm * 17 + c] = A[(size_t)(m0 + mm) * 1024 + c0 + c];
        }
        {
            int j = tid >> 2;
            int cq = (tid & 3) * 4;
            const float4 wv = *(const float4*)(Wo + (size_t)(j0 + j) * 1024 + c0 + cq);
            Bs[(cq + 0) * 64 + j] = wv.x;
            Bs[(cq + 1) * 64 + j] = wv.y;
            Bs[(cq + 2) * 64 + j] = wv.z;
            Bs[(cq + 3) * 64 + j] = wv.w;
        }
        __syncthreads();
#pragma unroll
        for (int c = 0; c < 16; c++) {
            float ar[4], br[4];
#pragma unroll
            for (int a = 0; a < 4; a++) ar[a] = As[(ty + 16 * a) * 17 + c];
#pragma unroll
            for (int u = 0; u < 4; u++) br[u] = Bs[c * 64 + tx + 16 * u];
#pragma unroll
            for (int a = 0; a < 4; a++)
#pragma unroll
                for (int u = 0; u < 4; u++) acc[a][u] += ar[a] * br[u];
        }
        __syncthreads();
    }

#pragma unroll
    for (int a = 0; a < 4; a++) {
        int row = m0 + ty + 16 * a;
#pragma unroll
        for (int u = 0; u < 4; u++) {
            int j = j0 + tx + 16 * u;
            out[(size_t)row * 1024 + j] = acc[a][u] + bo[j];
        }
    }
}

// ---------------------------------------------------------------------------
extern "C" void kernel_launch(void* const* d_in, const int* in_sizes, int n_in,
                              void* d_out, int out_size)
{
    const float* q   = (const float*)d_in[0];
    const float* k   = (const float*)d_in[1];
    const float* v   = (const float*)d_in[2];
    const float* Wq  = (const float*)d_in[3];
    const float* bq  = (const float*)d_in[4];
    const float* Wk  = (const float*)d_in[5];
    const float* bk  = (const float*)d_in[6];
    const float* Wv  = (const float*)d_in[7];
    const float* bv  = (const float*)d_in[8];
    const float* Wo  = (const float*)d_in[9];
    const float* bo  = (const float*)d_in[10];
    const int*   mask = (const int*)d_in[11];
    float* out = (float*)d_out;

    cudaFuncSetAttribute(conv_gemm_kernel,
                         cudaFuncAttributeMaxDynamicSharedMemorySize, GEMM_SMEM_BYTES);
    cudaFuncSetAttribute(attn_kernel,
                         cudaFuncAttributeMaxDynamicSharedMemorySize, ATTN_SMEM_BYTES);

    prep_a_kernel<<<dim3(1024, 3), 256>>>(Wq, Wk, Wv);
    prep_b_kernel<<<dim3(128, 24), 256>>>(q, k, v);
    conv_gemm_kernel<<<dim3(8, 8, 24), 256, GEMM_SMEM_BYTES>>>(bq, bk, bv);
    attn_kernel<<<dim3(16, 16, 8), 256, ATTN_SMEM_BYTES>>>(mask);
    proj_kernel<<<dim3(16, 128), 256>>>(Wo, bo, out);
}

// round 12
// speedup vs baseline: 11.3321x; 1.5782x over previous
#include <cuda_runtime.h>
#include <cuda_fp16.h>
#include <cuda_bf16.h>
#include <cstdint>
#include <math.h>

#define DIMC 1024
#define BATCH 8
#define NHEADS 16
#define HDIM 64

// ---------------------------------------------------------------------------
// Scratch (static device arrays: allocation-free rule)
// ---------------------------------------------------------------------------
__device__ float g_qc[BATCH * DIMC * DIMC];
__device__ float g_kc[BATCH * DIMC * DIMC];
__device__ float g_vc[BATCH * DIMC * DIMC];

// fp16 conv operands (unchanged from R10 — conv error stays bit-identical)
__device__ __half g_W16[3ULL * 1024 * 9216];
__device__ __half g_B16[24ULL * 1024 * 9216];

// bf16 hi/lo attention output (A of projection), [b*1024+t][1024]
__device__ __nv_bfloat16 g_aoh[BATCH * DIMC * DIMC];
__device__ __nv_bfloat16 g_aol[BATCH * DIMC * DIMC];
// bf16 hi/lo Wo, [j][c]
__device__ __nv_bfloat16 g_woh[DIMC * DIMC];
__device__ __nv_bfloat16 g_wol[DIMC * DIMC];

// ---------------------------------------------------------------------------
// Helpers (portable sm_80+ PTX only — tcgen05 rejected by this build's ptxas
// target sm_103 [no 'a']; ldmatrix + mma.sync HMMA path instead)
// ---------------------------------------------------------------------------
__device__ __forceinline__ uint32_t smem_u32(const void* p) {
    uint32_t a;
    asm("{ .reg .u64 t; cvta.to.shared.u64 t, %1; cvt.u32.u64 %0, t; }" : "=r"(a) : "l"(p));
    return a;
}

#define SWZ128(off) ((off) ^ (((off) >> 3) & 0x70))

__device__ __forceinline__ void ldsm_x4(uint32_t &r0, uint32_t &r1, uint32_t &r2, uint32_t &r3,
                                        uint32_t addr) {
    asm volatile("ldmatrix.sync.aligned.m8n8.x4.shared.b16 {%0,%1,%2,%3}, [%4];"
                 : "=r"(r0), "=r"(r1), "=r"(r2), "=r"(r3) : "r"(addr));
}
__device__ __forceinline__ void ldsm_x2(uint32_t &r0, uint32_t &r1, uint32_t addr) {
    asm volatile("ldmatrix.sync.aligned.m8n8.x2.shared.b16 {%0,%1}, [%2];"
                 : "=r"(r0), "=r"(r1) : "r"(addr));
}
__device__ __forceinline__ void ldsm_x2_t(uint32_t &r0, uint32_t &r1, uint32_t addr) {
    asm volatile("ldmatrix.sync.aligned.m8n8.x2.trans.shared.b16 {%0,%1}, [%2];"
                 : "=r"(r0), "=r"(r1) : "r"(addr));
}
__device__ __forceinline__ void mma16816_f16(float &c0, float &c1, float &c2, float &c3,
                                             uint32_t a0, uint32_t a1, uint32_t a2, uint32_t a3,
                                             uint32_t b0, uint32_t b1) {
    asm volatile("mma.sync.aligned.m16n8k16.row.col.f32.f16.f16.f32 "
                 "{%0,%1,%2,%3}, {%4,%5,%6,%7}, {%8,%9}, {%0,%1,%2,%3};"
                 : "+f"(c0), "+f"(c1), "+f"(c2), "+f"(c3)
                 : "r"(a0), "r"(a1), "r"(a2), "r"(a3), "r"(b0), "r"(b1));
}
__device__ __forceinline__ void mma16816_bf(float &c0, float &c1, float &c2, float &c3,
                                            uint32_t a0, uint32_t a1, uint32_t a2, uint32_t a3,
                                            uint32_t b0, uint32_t b1) {
    asm volatile("mma.sync.aligned.m16n8k16.row.col.f32.bf16.bf16.f32 "
                 "{%0,%1,%2,%3}, {%4,%5,%6,%7}, {%8,%9}, {%0,%1,%2,%3};"
                 : "+f"(c0), "+f"(c1), "+f"(c2), "+f"(c3)
                 : "r"(a0), "r"(a1), "r"(a2), "r"(a3), "r"(b0), "r"(b1));
}

// split 4 f32 -> bf16 hi/lo, store 8B each to shared
__device__ __forceinline__ void split_st8(float4 v, uint32_t addrH, uint32_t addrL) {
    __nv_bfloat16 h0 = __float2bfloat16(v.x), h1 = __float2bfloat16(v.y);
    __nv_bfloat16 h2 = __float2bfloat16(v.z), h3 = __float2bfloat16(v.w);
    uint32_t H0 = (uint32_t)__bfloat16_as_ushort(h0) | ((uint32_t)__bfloat16_as_ushort(h1) << 16);
    uint32_t H1 = (uint32_t)__bfloat16_as_ushort(h2) | ((uint32_t)__bfloat16_as_ushort(h3) << 16);
    float l0 = v.x - __bfloat162float(h0), l1 = v.y - __bfloat162float(h1);
    float l2 = v.z - __bfloat162float(h2), l3 = v.w - __bfloat162float(h3);
    uint32_t L0, L1;
    asm("cvt.rn.bf16x2.f32 %0, %1, %2;" : "=r"(L0) : "f"(l1), "f"(l0));
    asm("cvt.rn.bf16x2.f32 %0, %1, %2;" : "=r"(L1) : "f"(l3), "f"(l2));
    asm volatile("st.shared.v2.u32 [%0], {%1,%2};" :: "r"(addrH), "r"(H0), "r"(H1));
    asm volatile("st.shared.v2.u32 [%0], {%1,%2};" :: "r"(addrL), "r"(L0), "r"(L1));
}

// pack (a,b) -> bf16x2 hi/lo pair regs (a in lo half, b in hi half)
__device__ __forceinline__ void make_hl(float a, float b, uint32_t &h, uint32_t &l) {
    __nv_bfloat16 ha = __float2bfloat16(a), hb = __float2bfloat16(b);
    h = (uint32_t)__bfloat16_as_ushort(ha) | ((uint32_t)__bfloat16_as_ushort(hb) << 16);
    float la = a - __bfloat162float(ha), lb = b - __bfloat162float(hb);
    asm("cvt.rn.bf16x2.f32 %0, %1, %2;" : "=r"(l) : "f"(lb), "f"(la));
}

// ---------------------------------------------------------------------------
// prep_a: W[o][ic*9+t] f32 -> g_W16 [conv][o][t*1024+ic] fp16 (unchanged)
// ---------------------------------------------------------------------------
__global__ __launch_bounds__(256) void prep_a_kernel(
    const float* __restrict__ Wq, const float* __restrict__ Wk, const float* __restrict__ Wv)
{
    __shared__ float row[9216];
    const int conv = blockIdx.y, o = blockIdx.x, tid = threadIdx.x;
    const float* w = (conv == 0) ? Wq : (conv == 1) ? Wk : Wv;
    const float* src = w + (size_t)o * 9216;
    for (int i = tid; i < 9216; i += 256) row[i] = src[i];
    __syncthreads();

    __half* dh = g_W16 + ((size_t)conv * 1024 + o) * 9216;
    for (int g = tid; g < 1152; g += 256) {
        int t = g >> 7;
        int icb = (g & 127) * 8;
        unsigned int hw[4];
#pragma unroll
        for (int pr = 0; pr < 4; pr++) {
            __half h0 = __float2half_rn(row[(icb + pr * 2 + 0) * 9 + t]);
            __half h1 = __float2half_rn(row[(icb + pr * 2 + 1) * 9 + t]);
            hw[pr] = (unsigned)__half_as_ushort(h0) | ((unsigned)__half_as_ushort(h1) << 16);
        }
        uint4 hv4 = {hw[0], hw[1], hw[2], hw[3]};
        *(uint4*)(dh + (size_t)t * 1024 + icb) = hv4;
    }
}

// ---------------------------------------------------------------------------
// prep_b: im2col + fp16 convert (unchanged)
// ---------------------------------------------------------------------------
__global__ __launch_bounds__(256) void prep_b_kernel(
    const float* __restrict__ q, const float* __restrict__ k, const float* __restrict__ v)
{
    __shared__ float Xs[8 * 1024];
    const int cb = blockIdx.y;
    const int ic0 = blockIdx.x * 8;
    const int conv = cb >> 3, b = cb & 7;
    const float* src = ((conv == 0) ? q : (conv == 1) ? k : v) + ((size_t)b * 1024 + ic0) * 1024;
    for (int i = threadIdx.x; i < 8192; i += 256) Xs[i] = src[i];
    __syncthreads();

    __half* bh = g_B16 + (size_t)cb * 1024 * 9216;
    for (int e = threadIdx.x; e < 9216; e += 256) {
        int t = e >> 10;
        int p = e & 1023;
        int y = p >> 5, x = p & 31;
        int r = t / 3, c = t - r * 3;
        int sy = y + r - 1, sx = x + c - 1;
        bool ok = ((unsigned)sy < 32u) && ((unsigned)sx < 32u);
        int so = sy * 32 + sx;
        unsigned int hw[4];
#pragma unroll
        for (int pr = 0; pr < 4; pr++) {
            float v0 = ok ? Xs[(pr * 2 + 0) * 1024 + so] : 0.f;
            float v1 = ok ? Xs[(pr * 2 + 1) * 1024 + so] : 0.f;
            __half h0 = __float2half_rn(v0);
            __half h1 = __float2half_rn(v1);
            hw[pr] = (unsigned)__half_as_ushort(h0) | ((unsigned)__half_as_ushort(h1) << 16);
        }
        uint4 hv4 = {hw[0], hw[1], hw[2], hw[3]};
        *(uint4*)(bh + (size_t)p * 9216 + t * 1024 + ic0) = hv4;
    }
}

// ---------------------------------------------------------------------------
// wo_prep: Wo[j][c] f32 -> g_woh/g_wol bf16 hi/lo. grid 1024, 256 thr.
// FIXED: exactly one float4 per thread (256*4 = 1024 cols; R11's rep loop
// ran c4 to 4092 -> OOB read of Wo and OOB write of g_woh/g_wol).
// ---------------------------------------------------------------------------
__global__ __launch_bounds__(256) void wo_prep_kernel(const float* __restrict__ Wo)
{
    const int row = blockIdx.x, tid = threadIdx.x;
    const int c4 = tid * 4;
    float4 v = *(const float4*)(Wo + (size_t)row * 1024 + c4);
    __nv_bfloat16 h0 = __float2bfloat16(v.x), h1 = __float2bfloat16(v.y);
    __nv_bfloat16 h2 = __float2bfloat16(v.z), h3 = __float2bfloat16(v.w);
    uint2 H;
    H.x = (uint32_t)__bfloat16_as_ushort(h0) | ((uint32_t)__bfloat16_as_ushort(h1) << 16);
    H.y = (uint32_t)__bfloat16_as_ushort(h2) | ((uint32_t)__bfloat16_as_ushort(h3) << 16);
    float l0 = v.x - __bfloat162float(h0), l1 = v.y - __bfloat162float(h1);
    float l2 = v.z - __bfloat162float(h2), l3 = v.w - __bfloat162float(h3);
    uint2 L;
    asm("cvt.rn.bf16x2.f32 %0, %1, %2;" : "=r"(L.x) : "f"(l1), "f"(l0));
    asm("cvt.rn.bf16x2.f32 %0, %1, %2;" : "=r"(L.y) : "f"(l3), "f"(l2));
    *(uint2*)(g_woh + (size_t)row * 1024 + c4) = H;
    *(uint2*)(g_wol + (size_t)row * 1024 + c4) = L;
}

// ---------------------------------------------------------------------------
// conv GEMM via mma.sync (HMMA fp16, single term) — unchanged from R10
// ---------------------------------------------------------------------------
#define GEMM_SMEM_BYTES (65536 + 1024)
#define NSLICES 144

__global__ __launch_bounds__(256, 2) void conv_gemm_kernel(
    const float* __restrict__ bq, const float* __restrict__ bk, const float* __restrict__ bv)
{
    extern __shared__ char dynsmem[];
    const uint32_t raw = smem_u32(dynsmem);
    const uint32_t base = (raw + 1023u) & ~1023u;

    const int tid = threadIdx.x;
    const int wid = tid >> 5, lane = tid & 31;
    const int p0 = blockIdx.x * 128;
    const int o0 = blockIdx.y * 128;
    const int cb = blockIdx.z;
    const int conv = cb >> 3, b = cb & 7;

    const int wm = wid & 1;
    const int wn = wid >> 1;

    const __half* baseA = g_W16 + ((size_t)conv * 1024 + o0) * 9216;
    const __half* baseB = g_B16 + ((size_t)cb * 1024 + p0) * 9216;

    auto fill = [&](int bsel, int k0) {
#pragma unroll
        for (int j = 0; j < 8; j++) {
            const int sub = j >> 2;
            int qq = tid + 256 * (j & 3);
            int r = qq >> 3, c16 = qq & 7;
            uint32_t off = (uint32_t)(r * 128 + c16 * 16);
            uint32_t dst = base + (uint32_t)bsel * 32768u + (uint32_t)sub * 16384u + SWZ128(off);
            const __half* srcb = (sub == 0) ? baseA : baseB;
            const void* src = (const void*)(srcb + (size_t)r * 9216 + k0 + c16 * 8);
            asm volatile("cp.async.cg.shared.global [%0], [%1], 16;" :: "r"(dst), "l"(src));
        }
        asm volatile("cp.async.commit_group;");
    };

    float acc[4][4][4];
#pragma unroll
    for (int i = 0; i < 4; i++)
#pragma unroll
        for (int j = 0; j < 4; j++)
#pragma unroll
            for (int e = 0; e < 4; e++) acc[i][j][e] = 0.f;

    const int a_r  = lane & 15;
    const int a_c8 = (lane >> 4) * 8;
    const int b_r  = lane & 7;
    const int b_c8 = ((lane >> 3) & 1) * 8;

    fill(0, 0);

    for (int s = 0; s < NSLICES; s++) {
        const int bsel = s & 1;
        if (s + 1 < NSLICES) {
            fill(bsel ^ 1, (s + 1) * 64);
            asm volatile("cp.async.wait_group 1;");
        } else {
            asm volatile("cp.async.wait_group 0;");
        }
        __syncthreads();

        const uint32_t bb = base + (uint32_t)bsel * 32768u;
        const uint32_t bA = bb;
        const uint32_t bB = bb + 16384u;

#pragma unroll
        for (int kc = 0; kc < 64; kc += 16) {
            uint32_t ah[4][4];
#pragma unroll
            for (int i = 0; i < 4; i++) {
                uint32_t off = (uint32_t)((wm * 64 + i * 16 + a_r) * 128 + (kc + a_c8) * 2);
                ldsm_x4(ah[i][0], ah[i][1], ah[i][2], ah[i][3], bA + SWZ128(off));
            }
            uint32_t bh[4][2];
#pragma unroll
            for (int j = 0; j < 4; j++) {
                uint32_t off = (uint32_t)((wn * 32 + j * 8 + b_r) * 128 + (kc + b_c8) * 2);
                ldsm_x2(bh[j][0], bh[j][1], bB + SWZ128(off));
            }
#pragma unroll
            for (int i = 0; i < 4; i++)
#pragma unroll
                for (int j = 0; j < 4; j++)
                    mma16816_f16(acc[i][j][0], acc[i][j][1], acc[i][j][2], acc[i][j][3],
                                 ah[i][0], ah[i][1], ah[i][2], ah[i][3], bh[j][0], bh[j][1]);
        }
        __syncthreads();
    }

    float* outp = ((conv == 0) ? g_qc : (conv == 1) ? g_kc : g_vc) + (size_t)b * (DIMC * DIMC);
    const float* bias = (conv == 0) ? bq : (conv == 1) ? bk : bv;
    const int cr = lane >> 2;
    const int cc = (lane & 3) * 2;
#pragma unroll
    for (int i = 0; i < 4; i++) {
        const int o_lo = o0 + wm * 64 + i * 16 + cr;
        const int o_hi = o_lo + 8;
        const float bb0 = bias[o_lo];
        const float bb1 = bias[o_hi];
#pragma unroll
        for (int j = 0; j < 4; j++) {
            const int p = p0 + wn * 32 + j * 8 + cc;
            float2 v0 = {acc[i][j][0] + bb0, acc[i][j][1] + bb0};
            float2 v1 = {acc[i][j][2] + bb1, acc[i][j][3] + bb1};
            *(float2*)(outp + (size_t)o_lo * 1024 + p) = v0;
            *(float2*)(outp + (size_t)o_hi * 1024 + p) = v1;
        }
    }
}

// ---------------------------------------------------------------------------
// Tensor-core flash attention, bf16 3-term (QhKh+QhKl+QlKh; PhVh+PhVl+PlVh).
// Block: 256 thr = 8 warps; t-tile 128 (16 rows/warp, warp owns full s range).
// s-chunk 64, d = 64. P stays in registers (c-frag == a-frag layout).
// Epilogue writes AO as bf16 hi/lo for the projection GEMM.
// grid (8 t-tiles, 16 heads, 8 batch). smem 64KB (+align).
// ---------------------------------------------------------------------------
#define AT_QH 0
#define AT_QL 16384
#define AT_KH 32768
#define AT_KL 40960
#define AT_VH 49152
#define AT_VL 57344
#define ATTN_SMEM_BYTES (65536 + 1024)

__global__ __launch_bounds__(256, 2) void attn_mma_kernel(const int* __restrict__ mask)
{
    extern __shared__ char smemc[];
    const uint32_t sbase = (smem_u32(smemc) + 1023u) & ~1023u;

    const int tid = threadIdx.x;
    const int wid = tid >> 5, lane = tid & 31;
    const int t0 = blockIdx.x * 128;
    const int hd = blockIdx.y;
    const int b  = blockIdx.z;

    const float* Qg = g_qc + ((size_t)b * 1024 + t0) * 1024 + hd * HDIM;
    const float* Kg = g_kc + (size_t)b * 1024 * 1024 + hd * HDIM;   // row s added later
    const float* Vg = g_vc + (size_t)b * 1024 * 1024 + hd * HDIM;
    const int* mrow = mask + (size_t)b * 1024 * 1024;

    // Load + split Q tile [128][64] (once)
#pragma unroll
    for (int rep = 0; rep < 8; rep++) {
        int idx = tid + 256 * rep;              // 0..2047
        int t = idx >> 4;
        int d4 = (idx & 15) * 4;
        float4 qv = *(const float4*)(Qg + (size_t)t * 1024 + d4);
        uint32_t sw = SWZ128((uint32_t)(t * 128 + d4 * 2));
        split_st8(qv, sbase + AT_QH + sw, sbase + AT_QL + sw);
    }

    float m0 = -INFINITY, m1 = -INFINITY, l0 = 0.f, l1 = 0.f;
    float o[8][4];
#pragma unroll
    for (int j = 0; j < 8; j++)
#pragma unroll
        for (int e = 0; e < 4; e++) o[j][e] = 0.f;

    const float scale = 0.125f;
    const int r0 = lane >> 2;                   // row within warp's 16 (plus +8)
    const int qcol2 = (lane & 3) * 2;

    for (int s0 = 0; s0 < 1024; s0 += 64) {
        __syncthreads();   // prior chunk's V reads done before overwrite
        // Load + split K and V chunk [64][64] each
#pragma unroll
        for (int rep = 0; rep < 4; rep++) {
            int idx = tid + 256 * rep;
            int s = idx >> 4;
            int d4 = (idx & 15) * 4;
            uint32_t sw = SWZ128((uint32_t)(s * 128 + d4 * 2));
            float4 kv = *(const float4*)(Kg + (size_t)(s0 + s) * 1024 + d4);
            split_st8(kv, sbase + AT_KH + sw, sbase + AT_KL + sw);
            float4 vv = *(const float4*)(Vg + (size_t)(s0 + s) * 1024 + d4);
            split_st8(vv, sbase + AT_VH + sw, sbase + AT_VL + sw);
        }
        __syncthreads();

        // S = Q K^T  (bf16 3-term)
        float c[8][4];
#pragma unroll
        for (int j = 0; j < 8; j++)
#pragma unroll
            for (int e = 0; e < 4; e++) c[j][e] = 0.f;

#pragma unroll
        for (int kc = 0; kc < 64; kc += 16) {
            uint32_t aoff = SWZ128((uint32_t)((wid * 16 + (lane & 15)) * 128 + (kc + (lane >> 4) * 8) * 2));
            uint32_t ah0, ah1, ah2, ah3, al0, al1, al2, al3;
            ldsm_x4(ah0, ah1, ah2, ah3, sbase + AT_QH + aoff);
            ldsm_x4(al0, al1, al2, al3, sbase + AT_QL + aoff);
#pragma unroll
            for (int j = 0; j < 8; j++) {
                uint32_t boff = SWZ128((uint32_t)((j * 8 + (lane & 7)) * 128 + (kc + ((lane >> 3) & 1) * 8) * 2));
                uint32_t kh0, kh1, kl0, kl1;
                ldsm_x2(kh0, kh1, sbase + AT_KH + boff);
                ldsm_x2(kl0, kl1, sbase + AT_KL + boff);
                mma16816_bf(c[j][0], c[j][1], c[j][2], c[j][3], ah0, ah1, ah2, ah3, kh0, kh1);
                mma16816_bf(c[j][0], c[j][1], c[j][2], c[j][3], ah0, ah1, ah2, ah3, kl0, kl1);
                mma16816_bf(c[j][0], c[j][1], c[j][2], c[j][3], al0, al1, al2, al3, kh0, kh1);
            }
        }

        // scale + mask
        const int trg0 = t0 + wid * 16 + r0;
        const int* mr0 = mrow + (size_t)trg0 * 1024;
        const int* mr1 = mr0 + 8 * 1024;
#pragma unroll
        for (int j = 0; j < 8; j++) {
            int colg = s0 + j * 8 + qcol2;
            int2 q0 = *(const int2*)(mr0 + colg);
            int2 q1 = *(const int2*)(mr1 + colg);
            c[j][0] = q0.x ? c[j][0] * scale : -1e9f;
            c[j][1] = q0.y ? c[j][1] * scale : -1e9f;
            c[j][2] = q1.x ? c[j][2] * scale : -1e9f;
            c[j][3] = q1.y ? c[j][3] * scale : -1e9f;
        }

        // online softmax (rows r0, r0+8); lane-quad shfl covers all 64 cols
        float rm0 = -INFINITY, rm1 = -INFINITY;
#pragma unroll
        for (int j = 0; j < 8; j++) {
            rm0 = fmaxf(rm0, fmaxf(c[j][0], c[j][1]));
            rm1 = fmaxf(rm1, fmaxf(c[j][2], c[j][3]));
        }
        rm0 = fmaxf(rm0, __shfl_xor_sync(0xffffffffu, rm0, 1));
        rm0 = fmaxf(rm0, __shfl_xor_sync(0xffffffffu, rm0, 2));
        rm1 = fmaxf(rm1, __shfl_xor_sync(0xffffffffu, rm1, 1));
        rm1 = fmaxf(rm1, __shfl_xor_sync(0xffffffffu, rm1, 2));
        float mn0 = fmaxf(m0, rm0), mn1 = fmaxf(m1, rm1);
        float f0 = __expf(m0 - mn0), f1 = __expf(m1 - mn1);
        float sum0 = 0.f, sum1 = 0.f;
#pragma unroll
        for (int j = 0; j < 8; j++) {
            float p0 = __expf(c[j][0] - mn0); c[j][0] = p0; sum0 += p0;
            float p1 = __expf(c[j][1] - mn0); c[j][1] = p1; sum0 += p1;
            float p2 = __expf(c[j][2] - mn1); c[j][2] = p2; sum1 += p2;
            float p3 = __expf(c[j][3] - mn1); c[j][3] = p3; sum1 += p3;
        }
        sum0 += __shfl_xor_sync(0xffffffffu, sum0, 1);
        sum0 += __shfl_xor_sync(0xffffffffu, sum0, 2);
        sum1 += __shfl_xor_sync(0xffffffffu, sum1, 1);
        sum1 += __shfl_xor_sync(0xffffffffu, sum1, 2);
        l0 = l0 * f0 + sum0; l1 = l1 * f1 + sum1;
        m0 = mn0; m1 = mn1;
#pragma unroll
        for (int j = 0; j < 8; j++) {
            o[j][0] *= f0; o[j][1] *= f0;
            o[j][2] *= f1; o[j][3] *= f1;
        }

        // O += P V   (P a-frag built from c-frags in registers)
#pragma unroll
        for (int kk = 0; kk < 4; kk++) {
            const int ja = kk * 2, jb = kk * 2 + 1;
            uint32_t ph0, ph1, ph2, ph3, pl0, pl1, pl2, pl3;
            make_hl(c[ja][0], c[ja][1], ph0, pl0);
            make_hl(c[ja][2], c[ja][3], ph1, pl1);
            make_hl(c[jb][0], c[jb][1], ph2, pl2);
            make_hl(c[jb][2], c[jb][3], ph3, pl3);
#pragma unroll
            for (int jd = 0; jd < 8; jd++) {
                uint32_t voff = SWZ128((uint32_t)((kk * 16 + (lane & 15)) * 128 + jd * 16));
                uint32_t vh0, vh1, vl0, vl1;
                ldsm_x2_t(vh0, vh1, sbase + AT_VH + voff);
                ldsm_x2_t(vl0, vl1, sbase + AT_VL + voff);
                mma16816_bf(o[jd][0], o[jd][1], o[jd][2], o[jd][3], ph0, ph1, ph2, ph3, vh0, vh1);
                mma16816_bf(o[jd][0], o[jd][1], o[jd][2], o[jd][3], ph0, ph1, ph2, ph3, vl0, vl1);
                mma16816_bf(o[jd][0], o[jd][1], o[jd][2], o[jd][3], pl0, pl1, pl2, pl3, vh0, vh1);
            }
        }
    }

    // Epilogue: normalize, split to bf16 hi/lo, store AO
    float inv0 = 1.f / l0, inv1 = 1.f / l1;
    size_t row0 = (size_t)b * 1024 + t0 + wid * 16 + r0;
    size_t row1 = row0 + 8;
#pragma unroll
    for (int jd = 0; jd < 8; jd++) {
        int colg = hd * HDIM + jd * 8 + qcol2;
        uint32_t h, lz;
        make_hl(o[jd][0] * inv0, o[jd][1] * inv0, h, lz);
        *(uint32_t*)(g_aoh + row0 * 1024 + colg) = h;
        *(uint32_t*)(g_aol + row0 * 1024 + colg) = lz;
        make_hl(o[jd][2] * inv1, o[jd][3] * inv1, h, lz);
        *(uint32_t*)(g_aoh + row1 * 1024 + colg) = h;
        *(uint32_t*)(g_aol + row1 * 1024 + colg) = lz;
    }
}

// ---------------------------------------------------------------------------
// Projection GEMM, bf16 3-term: out[m][j] = sum_c AO[m][c]*Wo[j][c] + bo[j]
// Tile 128x128, K=1024 in 16 slices of 64, double-buffered cp.async.
// grid (8 j-tiles, 64 m-tiles), 256 thr, 129KB smem.
// ---------------------------------------------------------------------------
#define PROJ_SMEM_BYTES (131072 + 1024)

__global__ __launch_bounds__(256, 1) void proj_gemm_kernel(
    const float* __restrict__ bo, float* __restrict__ out)
{
    extern __shared__ char dynp[];
    const uint32_t base = (smem_u32(dynp) + 1023u) & ~1023u;

    const int tid = threadIdx.x;
    const int wid = tid >> 5, lane = tid & 31;
    const int j0 = blockIdx.x * 128;
    const int m0 = blockIdx.y * 128;
    const int wm = wid & 1;
    const int wn = wid >> 1;

    const __nv_bfloat16* bases[4] = {
        g_aoh + (size_t)m0 * 1024,
        g_aol + (size_t)m0 * 1024,
        g_woh + (size_t)j0 * 1024,
        g_wol + (size_t)j0 * 1024,
    };

    auto fill = [&](int bsel, int k0) {
#pragma unroll
        for (int j = 0; j < 16; j++) {
            const int sub = j >> 2;                 // 0:Ah 1:Al 2:Bh 3:Bl
            int qq = tid + 256 * (j & 3);
            int r = qq >> 3, c16 = qq & 7;
            uint32_t off = (uint32_t)(r * 128 + c16 * 16);
            uint32_t dst = base + (uint32_t)bsel * 65536u + (uint32_t)sub * 16384u + SWZ128(off);
            const void* src = (const void*)(bases[sub] + (size_t)r * 1024 + k0 + c16 * 8);
            asm volatile("cp.async.cg.shared.global [%0], [%1], 16;" :: "r"(dst), "l"(src));
        }
        asm volatile("cp.async.commit_group;");
    };

    float acc[4][4][4];
#pragma unroll
    for (int i = 0; i < 4; i++)
#pragma unroll
        for (int j = 0; j < 4; j++)
#pragma unroll
            for (int e = 0; e < 4; e++) acc[i][j][e] = 0.f;

    const int a_r  = lane & 15;
    const int a_c8 = (lane >> 4) * 8;
    const int b_r  = lane & 7;
    const int b_c8 = ((lane >> 3) & 1) * 8;

    fill(0, 0);

    for (int s = 0; s < 16; s++) {
        const int bsel = s & 1;
        if (s + 1 < 16) {
            fill(bsel ^ 1, (s + 1) * 64);
            asm volatile("cp.async.wait_group 1;");
        } else {
            asm volatile("cp.async.wait_group 0;");
        }
        __syncthreads();

        const uint32_t bb  = base + (uint32_t)bsel * 65536u;
        const uint32_t bAh = bb;
        const uint32_t bAl = bb + 16384u;
        const uint32_t bBh = bb + 32768u;
        const uint32_t bBl = bb + 49152u;

#pragma unroll
        for (int kc = 0; kc < 64; kc += 16) {
            uint32_t ah[4][4], al[4][4];
#pragma unroll
            for (int i = 0; i < 4; i++) {
                uint32_t off = (uint32_t)((wm * 64 + i * 16 + a_r) * 128 + (kc + a_c8) * 2);
                uint32_t sw = SWZ128(off);
                ldsm_x4(ah[i][0], ah[i][1], ah[i][2], ah[i][3], bAh + sw);
                ldsm_x4(al[i][0], al[i][1], al[i][2], al[i][3], bAl + sw);
            }
            uint32_t bh[4][2], bl[4][2];
#pragma unroll
            for (int j = 0; j < 4; j++) {
                uint32_t off = (uint32_t)((wn * 32 + j * 8 + b_r) * 128 + (kc + b_c8) * 2);
                uint32_t sw = SWZ128(off);
                ldsm_x2(bh[j][0], bh[j][1], bBh + sw);
                ldsm_x2(bl[j][0], bl[j][1], bBl + sw);
            }
#pragma unroll
            for (int i = 0; i < 4; i++)
#pragma unroll
                for (int j = 0; j < 4; j++) {
                    mma16816_bf(acc[i][j][0], acc[i][j][1], acc[i][j][2], acc[i][j][3],
                                ah[i][0], ah[i][1], ah[i][2], ah[i][3], bh[j][0], bh[j][1]);
                    mma16816_bf(acc[i][j][0], acc[i][j][1], acc[i][j][2], acc[i][j][3],
                                ah[i][0], ah[i][1], ah[i][2], ah[i][3], bl[j][0], bl[j][1]);
                    mma16816_bf(acc[i][j][0], acc[i][j][1], acc[i][j][2], acc[i][j][3],
                                al[i][0], al[i][1], al[i][2], al[i][3], bh[j][0], bh[j][1]);
                }
        }
        __syncthreads();
    }

    const int cr = lane >> 2;
    const int cc = (lane & 3) * 2;
#pragma unroll
    for (int i = 0; i < 4; i++) {
        const int r_lo = m0 + wm * 64 + i * 16 + cr;
        const int r_hi = r_lo + 8;
#pragma unroll
        for (int j = 0; j < 4; j++) {
            const int p = j0 + wn * 32 + j * 8 + cc;
            float2 bb = *(const float2*)(bo + p);
            float2 v0 = {acc[i][j][0] + bb.x, acc[i][j][1] + bb.y};
            float2 v1 = {acc[i][j][2] + bb.x, acc[i][j][3] + bb.y};
            *(float2*)(out + (size_t)r_lo * 1024 + p) = v0;
            *(float2*)(out + (size_t)r_hi * 1024 + p) = v1;
        }
    }
}

// ---------------------------------------------------------------------------
extern "C" void kernel_launch(void* const* d_in, const int* in_sizes, int n_in,
                              void* d_out, int out_size)
{
    const float* q   = (const float*)d_in[0];
    const float* k   = (const float*)d_in[1];
    const float* v   = (const float*)d_in[2];
    const float* Wq  = (const float*)d_in[3];
    const float* bq  = (const float*)d_in[4];
    const float* Wk  = (const float*)d_in[5];
    const float* bk  = (const float*)d_in[6];
    const float* Wv  = (const float*)d_in[7];
    const float* bv  = (const float*)d_in[8];
    const float* Wo  = (const float*)d_in[9];
    const float* bo  = (const float*)d_in[10];
    const int*   mask = (const int*)d_in[11];
    float* out = (float*)d_out;

    cudaFuncSetAttribute(conv_gemm_kernel,
                         cudaFuncAttributeMaxDynamicSharedMemorySize, GEMM_SMEM_BYTES);
    cudaFuncSetAttribute(attn_mma_kernel,
                         cudaFuncAttributeMaxDynamicSharedMemorySize, ATTN_SMEM_BYTES);
    cudaFuncSetAttribute(proj_gemm_kernel,
                         cudaFuncAttributeMaxDynamicSharedMemorySize, PROJ_SMEM_BYTES);

    prep_a_kernel<<<dim3(1024, 3), 256>>>(Wq, Wk, Wv);
    prep_b_kernel<<<dim3(128, 24), 256>>>(q, k, v);
    wo_prep_kernel<<<1024, 256>>>(Wo);
    conv_gemm_kernel<<<dim3(8, 8, 24), 256, GEMM_SMEM_BYTES>>>(bq, bk, bv);
    attn_mma_kernel<<<dim3(8, 16, 8), 256, ATTN_SMEM_BYTES>>>(mask);
    proj_gemm_kernel<<<dim3(8, 64), 256, PROJ_SMEM_BYTES>>>(bo, out);
}

// round 13
// speedup vs baseline: 11.6402x; 1.0272x over previous
#include <cuda_runtime.h>
#include <cuda_fp16.h>
#include <cuda_bf16.h>
#include <cstdint>
#include <math.h>

#define DIMC 1024
#define BATCH 8
#define NHEADS 16
#define HDIM 64

// ---------------------------------------------------------------------------
// Scratch (static device arrays: allocation-free rule)
// ---------------------------------------------------------------------------
__device__ float g_qc[BATCH * DIMC * DIMC];
__device__ float g_kc[BATCH * DIMC * DIMC];
__device__ float g_vc[BATCH * DIMC * DIMC];

// fp16 conv operands (unchanged — conv error stays bit-identical)
__device__ __half g_W16[3ULL * 1024 * 9216];
__device__ __half g_B16[24ULL * 1024 * 9216];

// bf16 hi/lo attention output (A of projection), [b*1024+t][1024]
__device__ __nv_bfloat16 g_aoh[BATCH * DIMC * DIMC];
__device__ __nv_bfloat16 g_aol[BATCH * DIMC * DIMC];
// bf16 hi/lo Wo, [j][c]
__device__ __nv_bfloat16 g_woh[DIMC * DIMC];
__device__ __nv_bfloat16 g_wol[DIMC * DIMC];

// ---------------------------------------------------------------------------
// Helpers (portable sm_80+ PTX only — tcgen05 rejected by this build's ptxas
// target sm_103 [no 'a']; ldmatrix + mma.sync HMMA path instead)
// ---------------------------------------------------------------------------
__device__ __forceinline__ uint32_t smem_u32(const void* p) {
    uint32_t a;
    asm("{ .reg .u64 t; cvta.to.shared.u64 t, %1; cvt.u32.u64 %0, t; }" : "=r"(a) : "l"(p));
    return a;
}

#define SWZ128(off) ((off) ^ (((off) >> 3) & 0x70))

__device__ __forceinline__ void ldsm_x4(uint32_t &r0, uint32_t &r1, uint32_t &r2, uint32_t &r3,
                                        uint32_t addr) {
    asm volatile("ldmatrix.sync.aligned.m8n8.x4.shared.b16 {%0,%1,%2,%3}, [%4];"
                 : "=r"(r0), "=r"(r1), "=r"(r2), "=r"(r3) : "r"(addr));
}
__device__ __forceinline__ void ldsm_x2(uint32_t &r0, uint32_t &r1, uint32_t addr) {
    asm volatile("ldmatrix.sync.aligned.m8n8.x2.shared.b16 {%0,%1}, [%2];"
                 : "=r"(r0), "=r"(r1) : "r"(addr));
}
__device__ __forceinline__ void ldsm_x2_t(uint32_t &r0, uint32_t &r1, uint32_t addr) {
    asm volatile("ldmatrix.sync.aligned.m8n8.x2.trans.shared.b16 {%0,%1}, [%2];"
                 : "=r"(r0), "=r"(r1) : "r"(addr));
}
__device__ __forceinline__ void mma16816_f16(float &c0, float &c1, float &c2, float &c3,
                                             uint32_t a0, uint32_t a1, uint32_t a2, uint32_t a3,
                                             uint32_t b0, uint32_t b1) {
    asm volatile("mma.sync.aligned.m16n8k16.row.col.f32.f16.f16.f32 "
                 "{%0,%1,%2,%3}, {%4,%5,%6,%7}, {%8,%9}, {%0,%1,%2,%3};"
                 : "+f"(c0), "+f"(c1), "+f"(c2), "+f"(c3)
                 : "r"(a0), "r"(a1), "r"(a2), "r"(a3), "r"(b0), "r"(b1));
}
__device__ __forceinline__ void mma16816_bf(float &c0, float &c1, float &c2, float &c3,
                                            uint32_t a0, uint32_t a1, uint32_t a2, uint32_t a3,
                                            uint32_t b0, uint32_t b1) {
    asm volatile("mma.sync.aligned.m16n8k16.row.col.f32.bf16.bf16.f32 "
                 "{%0,%1,%2,%3}, {%4,%5,%6,%7}, {%8,%9}, {%0,%1,%2,%3};"
                 : "+f"(c0), "+f"(c1), "+f"(c2), "+f"(c3)
                 : "r"(a0), "r"(a1), "r"(a2), "r"(a3), "r"(b0), "r"(b1));
}

// split 4 f32 -> bf16 hi/lo, store 8B each to shared
__device__ __forceinline__ void split_st8(float4 v, uint32_t addrH, uint32_t addrL) {
    __nv_bfloat16 h0 = __float2bfloat16(v.x), h1 = __float2bfloat16(v.y);
    __nv_bfloat16 h2 = __float2bfloat16(v.z), h3 = __float2bfloat16(v.w);
    uint32_t H0 = (uint32_t)__bfloat16_as_ushort(h0) | ((uint32_t)__bfloat16_as_ushort(h1) << 16);
    uint32_t H1 = (uint32_t)__bfloat16_as_ushort(h2) | ((uint32_t)__bfloat16_as_ushort(h3) << 16);
    float l0 = v.x - __bfloat162float(h0), l1 = v.y - __bfloat162float(h1);
    float l2 = v.z - __bfloat162float(h2), l3 = v.w - __bfloat162float(h3);
    uint32_t L0, L1;
    asm("cvt.rn.bf16x2.f32 %0, %1, %2;" : "=r"(L0) : "f"(l1), "f"(l0));
    asm("cvt.rn.bf16x2.f32 %0, %1, %2;" : "=r"(L1) : "f"(l3), "f"(l2));
    asm volatile("st.shared.v2.u32 [%0], {%1,%2};" :: "r"(addrH), "r"(H0), "r"(H1));
    asm volatile("st.shared.v2.u32 [%0], {%1,%2};" :: "r"(addrL), "r"(L0), "r"(L1));
}

// pack (a,b) -> bf16x2 hi/lo pair regs (a in lo half, b in hi half)
__device__ __forceinline__ void make_hl(float a, float b, uint32_t &h, uint32_t &l) {
    __nv_bfloat16 ha = __float2bfloat16(a), hb = __float2bfloat16(b);
    h = (uint32_t)__bfloat16_as_ushort(ha) | ((uint32_t)__bfloat16_as_ushort(hb) << 16);
    float la = a - __bfloat162float(ha), lb = b - __bfloat162float(hb);
    asm("cvt.rn.bf16x2.f32 %0, %1, %2;" : "=r"(l) : "f"(lb), "f"(la));
}

// ---------------------------------------------------------------------------
// prep_a: W[o][ic*9+t] f32 -> g_W16 [conv][o][t*1024+ic] fp16 (unchanged)
// ---------------------------------------------------------------------------
__global__ __launch_bounds__(256) void prep_a_kernel(
    const float* __restrict__ Wq, const float* __restrict__ Wk, const float* __restrict__ Wv)
{
    __shared__ float row[9216];
    const int conv = blockIdx.y, o = blockIdx.x, tid = threadIdx.x;
    const float* w = (conv == 0) ? Wq : (conv == 1) ? Wk : Wv;
    const float* src = w + (size_t)o * 9216;
    for (int i = tid; i < 9216; i += 256) row[i] = src[i];
    __syncthreads();

    __half* dh = g_W16 + ((size_t)conv * 1024 + o) * 9216;
    for (int g = tid; g < 1152; g += 256) {
        int t = g >> 7;
        int icb = (g & 127) * 8;
        unsigned int hw[4];
#pragma unroll
        for (int pr = 0; pr < 4; pr++) {
            __half h0 = __float2half_rn(row[(icb + pr * 2 + 0) * 9 + t]);
            __half h1 = __float2half_rn(row[(icb + pr * 2 + 1) * 9 + t]);
            hw[pr] = (unsigned)__half_as_ushort(h0) | ((unsigned)__half_as_ushort(h1) << 16);
        }
        uint4 hv4 = {hw[0], hw[1], hw[2], hw[3]};
        *(uint4*)(dh + (size_t)t * 1024 + icb) = hv4;
    }
}

// ---------------------------------------------------------------------------
// prep_b: im2col + fp16 convert (unchanged)
// ---------------------------------------------------------------------------
__global__ __launch_bounds__(256) void prep_b_kernel(
    const float* __restrict__ q, const float* __restrict__ k, const float* __restrict__ v)
{
    __shared__ float Xs[8 * 1024];
    const int cb = blockIdx.y;
    const int ic0 = blockIdx.x * 8;
    const int conv = cb >> 3, b = cb & 7;
    const float* src = ((conv == 0) ? q : (conv == 1) ? k : v) + ((size_t)b * 1024 + ic0) * 1024;
    for (int i = threadIdx.x; i < 8192; i += 256) Xs[i] = src[i];
    __syncthreads();

    __half* bh = g_B16 + (size_t)cb * 1024 * 9216;
    for (int e = threadIdx.x; e < 9216; e += 256) {
        int t = e >> 10;
        int p = e & 1023;
        int y = p >> 5, x = p & 31;
        int r = t / 3, c = t - r * 3;
        int sy = y + r - 1, sx = x + c - 1;
        bool ok = ((unsigned)sy < 32u) && ((unsigned)sx < 32u);
        int so = sy * 32 + sx;
        unsigned int hw[4];
#pragma unroll
        for (int pr = 0; pr < 4; pr++) {
            float v0 = ok ? Xs[(pr * 2 + 0) * 1024 + so] : 0.f;
            float v1 = ok ? Xs[(pr * 2 + 1) * 1024 + so] : 0.f;
            __half h0 = __float2half_rn(v0);
            __half h1 = __float2half_rn(v1);
            hw[pr] = (unsigned)__half_as_ushort(h0) | ((unsigned)__half_as_ushort(h1) << 16);
        }
        uint4 hv4 = {hw[0], hw[1], hw[2], hw[3]};
        *(uint4*)(bh + (size_t)p * 9216 + t * 1024 + ic0) = hv4;
    }
}

// ---------------------------------------------------------------------------
// wo_prep: Wo[j][c] f32 -> g_woh/g_wol bf16 hi/lo. One float4 per thread.
// ---------------------------------------------------------------------------
__global__ __launch_bounds__(256) void wo_prep_kernel(const float* __restrict__ Wo)
{
    const int row = blockIdx.x, tid = threadIdx.x;
    const int c4 = tid * 4;
    float4 v = *(const float4*)(Wo + (size_t)row * 1024 + c4);
    __nv_bfloat16 h0 = __float2bfloat16(v.x), h1 = __float2bfloat16(v.y);
    __nv_bfloat16 h2 = __float2bfloat16(v.z), h3 = __float2bfloat16(v.w);
    uint2 H;
    H.x = (uint32_t)__bfloat16_as_ushort(h0) | ((uint32_t)__bfloat16_as_ushort(h1) << 16);
    H.y = (uint32_t)__bfloat16_as_ushort(h2) | ((uint32_t)__bfloat16_as_ushort(h3) << 16);
    float l0 = v.x - __bfloat162float(h0), l1 = v.y - __bfloat162float(h1);
    float l2 = v.z - __bfloat162float(h2), l3 = v.w - __bfloat162float(h3);
    uint2 L;
    asm("cvt.rn.bf16x2.f32 %0, %1, %2;" : "=r"(L.x) : "f"(l1), "f"(l0));
    asm("cvt.rn.bf16x2.f32 %0, %1, %2;" : "=r"(L.y) : "f"(l3), "f"(l2));
    *(uint2*)(g_woh + (size_t)row * 1024 + c4) = H;
    *(uint2*)(g_wol + (size_t)row * 1024 + c4) = L;
}

// ---------------------------------------------------------------------------
// conv GEMM via mma.sync (HMMA fp16, single term):
// R13: 4 warps / 128 threads, warp tile 64x64 (2x2 warp grid) -> 128 B of
// LDSM traffic per HMMA (was 192) to unthrottle the tensor pipe (ncu R12:
// tensor 67%, L1 58%). Same 128x128 CTA tile, K-slice 64, double-buffered
// cp.async, SW128 swizzle. grid (8 p, 8 o, 24), 66KB smem, 2 CTAs/SM.
// ---------------------------------------------------------------------------
#define GEMM_SMEM_BYTES (65536 + 1024)
#define NSLICES 144

__global__ __launch_bounds__(128, 2) void conv_gemm_kernel(
    const float* __restrict__ bq, const float* __restrict__ bk, const float* __restrict__ bv)
{
    extern __shared__ char dynsmem[];
    const uint32_t raw = smem_u32(dynsmem);
    const uint32_t base = (raw + 1023u) & ~1023u;

    const int tid = threadIdx.x;
    const int wid = tid >> 5, lane = tid & 31;
    const int p0 = blockIdx.x * 128;
    const int o0 = blockIdx.y * 128;
    const int cb = blockIdx.z;
    const int conv = cb >> 3, b = cb & 7;

    const int wm = wid & 1;          // M group of 64
    const int wn = wid >> 1;         // N group of 64

    const __half* baseA = g_W16 + ((size_t)conv * 1024 + o0) * 9216;
    const __half* baseB = g_B16 + ((size_t)cb * 1024 + p0) * 9216;

    auto fill = [&](int bsel, int k0) {
#pragma unroll
        for (int j = 0; j < 16; j++) {
            const int sub = j >> 3;                 // 0:A 1:B
            int qq = tid + 128 * (j & 7);           // 0..1023 in sub-buffer
            int r = qq >> 3, c16 = qq & 7;          // row 0..127, 16B chunk
            uint32_t off = (uint32_t)(r * 128 + c16 * 16);
            uint32_t dst = base + (uint32_t)bsel * 32768u + (uint32_t)sub * 16384u + SWZ128(off);
            const __half* srcb = (sub == 0) ? baseA : baseB;
            const void* src = (const void*)(srcb + (size_t)r * 9216 + k0 + c16 * 8);
            asm volatile("cp.async.cg.shared.global [%0], [%1], 16;" :: "r"(dst), "l"(src));
        }
        asm volatile("cp.async.commit_group;");
    };

    float acc[4][8][4];
#pragma unroll
    for (int i = 0; i < 4; i++)
#pragma unroll
        for (int j = 0; j < 8; j++)
#pragma unroll
            for (int e = 0; e < 4; e++) acc[i][j][e] = 0.f;

    const int a_r  = lane & 15;
    const int a_c8 = (lane >> 4) * 8;
    const int b_r  = lane & 7;
    const int b_c8 = ((lane >> 3) & 1) * 8;

    fill(0, 0);

    for (int s = 0; s < NSLICES; s++) {
        const int bsel = s & 1;
        if (s + 1 < NSLICES) {
            fill(bsel ^ 1, (s + 1) * 64);
            asm volatile("cp.async.wait_group 1;");
        } else {
            asm volatile("cp.async.wait_group 0;");
        }
        __syncthreads();

        const uint32_t bb = base + (uint32_t)bsel * 32768u;
        const uint32_t bA = bb;
        const uint32_t bB = bb + 16384u;

#pragma unroll
        for (int kc = 0; kc < 64; kc += 16) {
            uint32_t ah[4][4];
#pragma unroll
            for (int i = 0; i < 4; i++) {
                uint32_t off = (uint32_t)((wm * 64 + i * 16 + a_r) * 128 + (kc + a_c8) * 2);
                ldsm_x4(ah[i][0], ah[i][1], ah[i][2], ah[i][3], bA + SWZ128(off));
            }
            uint32_t bh[8][2];
#pragma unroll
            for (int j = 0; j < 8; j++) {
                uint32_t off = (uint32_t)((wn * 64 + j * 8 + b_r) * 128 + (kc + b_c8) * 2);
                ldsm_x2(bh[j][0], bh[j][1], bB + SWZ128(off));
            }
#pragma unroll
            for (int i = 0; i < 4; i++)
#pragma unroll
                for (int j = 0; j < 8; j++)
                    mma16816_f16(acc[i][j][0], acc[i][j][1], acc[i][j][2], acc[i][j][3],
                                 ah[i][0], ah[i][1], ah[i][2], ah[i][3], bh[j][0], bh[j][1]);
        }
        __syncthreads();
    }

    float* outp = ((conv == 0) ? g_qc : (conv == 1) ? g_kc : g_vc) + (size_t)b * (DIMC * DIMC);
    const float* bias = (conv == 0) ? bq : (conv == 1) ? bk : bv;
    const int cr = lane >> 2;
    const int cc = (lane & 3) * 2;
#pragma unroll
    for (int i = 0; i < 4; i++) {
        const int o_lo = o0 + wm * 64 + i * 16 + cr;
        const int o_hi = o_lo + 8;
        const float bb0 = bias[o_lo];
        const float bb1 = bias[o_hi];
#pragma unroll
        for (int j = 0; j < 8; j++) {
            const int p = p0 + wn * 64 + j * 8 + cc;
            float2 v0 = {acc[i][j][0] + bb0, acc[i][j][1] + bb0};
            float2 v1 = {acc[i][j][2] + bb1, acc[i][j][3] + bb1};
            *(float2*)(outp + (size_t)o_lo * 1024 + p) = v0;
            *(float2*)(outp + (size_t)o_hi * 1024 + p) = v1;
        }
    }
}

// ---------------------------------------------------------------------------
// Tensor-core flash attention, bf16 3-term (unchanged from passing R12)
// ---------------------------------------------------------------------------
#define AT_QH 0
#define AT_QL 16384
#define AT_KH 32768
#define AT_KL 40960
#define AT_VH 49152
#define AT_VL 57344
#define ATTN_SMEM_BYTES (65536 + 1024)

__global__ __launch_bounds__(256, 2) void attn_mma_kernel(const int* __restrict__ mask)
{
    extern __shared__ char smemc[];
    const uint32_t sbase = (smem_u32(smemc) + 1023u) & ~1023u;

    const int tid = threadIdx.x;
    const int wid = tid >> 5, lane = tid & 31;
    const int t0 = blockIdx.x * 128;
    const int hd = blockIdx.y;
    const int b  = blockIdx.z;

    const float* Qg = g_qc + ((size_t)b * 1024 + t0) * 1024 + hd * HDIM;
    const float* Kg = g_kc + (size_t)b * 1024 * 1024 + hd * HDIM;
    const float* Vg = g_vc + (size_t)b * 1024 * 1024 + hd * HDIM;
    const int* mrow = mask + (size_t)b * 1024 * 1024;

#pragma unroll
    for (int rep = 0; rep < 8; rep++) {
        int idx = tid + 256 * rep;
        int t = idx >> 4;
        int d4 = (idx & 15) * 4;
        float4 qv = *(const float4*)(Qg + (size_t)t * 1024 + d4);
        uint32_t sw = SWZ128((uint32_t)(t * 128 + d4 * 2));
        split_st8(qv, sbase + AT_QH + sw, sbase + AT_QL + sw);
    }

    float m0 = -INFINITY, m1 = -INFINITY, l0 = 0.f, l1 = 0.f;
    float o[8][4];
#pragma unroll
    for (int j = 0; j < 8; j++)
#pragma unroll
        for (int e = 0; e < 4; e++) o[j][e] = 0.f;

    const float scale = 0.125f;
    const int r0 = lane >> 2;
    const int qcol2 = (lane & 3) * 2;

    for (int s0 = 0; s0 < 1024; s0 += 64) {
        __syncthreads();
#pragma unroll
        for (int rep = 0; rep < 4; rep++) {
            int idx = tid + 256 * rep;
            int s = idx >> 4;
            int d4 = (idx & 15) * 4;
            uint32_t sw = SWZ128((uint32_t)(s * 128 + d4 * 2));
            float4 kv = *(const float4*)(Kg + (size_t)(s0 + s) * 1024 + d4);
            split_st8(kv, sbase + AT_KH + sw, sbase + AT_KL + sw);
            float4 vv = *(const float4*)(Vg + (size_t)(s0 + s) * 1024 + d4);
            split_st8(vv, sbase + AT_VH + sw, sbase + AT_VL + sw);
        }
        __syncthreads();

        float c[8][4];
#pragma unroll
        for (int j = 0; j < 8; j++)
#pragma unroll
            for (int e = 0; e < 4; e++) c[j][e] = 0.f;

#pragma unroll
        for (int kc = 0; kc < 64; kc += 16) {
            uint32_t aoff = SWZ128((uint32_t)((wid * 16 + (lane & 15)) * 128 + (kc + (lane >> 4) * 8) * 2));
            uint32_t ah0, ah1, ah2, ah3, al0, al1, al2, al3;
            ldsm_x4(ah0, ah1, ah2, ah3, sbase + AT_QH + aoff);
            ldsm_x4(al0, al1, al2, al3, sbase + AT_QL + aoff);
#pragma unroll
            for (int j = 0; j < 8; j++) {
                uint32_t boff = SWZ128((uint32_t)((j * 8 + (lane & 7)) * 128 + (kc + ((lane >> 3) & 1) * 8) * 2));
                uint32_t kh0, kh1, kl0, kl1;
                ldsm_x2(kh0, kh1, sbase + AT_KH + boff);
                ldsm_x2(kl0, kl1, sbase + AT_KL + boff);
                mma16816_bf(c[j][0], c[j][1], c[j][2], c[j][3], ah0, ah1, ah2, ah3, kh0, kh1);
                mma16816_bf(c[j][0], c[j][1], c[j][2], c[j][3], ah0, ah1, ah2, ah3, kl0, kl1);
                mma16816_bf(c[j][0], c[j][1], c[j][2], c[j][3], al0, al1, al2, al3, kh0, kh1);
            }
        }

        const int trg0 = t0 + wid * 16 + r0;
        const int* mr0 = mrow + (size_t)trg0 * 1024;
        const int* mr1 = mr0 + 8 * 1024;
#pragma unroll
        for (int j = 0; j < 8; j++) {
            int colg = s0 + j * 8 + qcol2;
            int2 q0 = *(const int2*)(mr0 + colg);
            int2 q1 = *(const int2*)(mr1 + colg);
            c[j][0] = q0.x ? c[j][0] * scale : -1e9f;
            c[j][1] = q0.y ? c[j][1] * scale : -1e9f;
            c[j][2] = q1.x ? c[j][2] * scale : -1e9f;
            c[j][3] = q1.y ? c[j][3] * scale : -1e9f;
        }

        float rm0 = -INFINITY, rm1 = -INFINITY;
#pragma unroll
        for (int j = 0; j < 8; j++) {
            rm0 = fmaxf(rm0, fmaxf(c[j][0], c[j][1]));
            rm1 = fmaxf(rm1, fmaxf(c[j][2], c[j][3]));
        }
        rm0 = fmaxf(rm0, __shfl_xor_sync(0xffffffffu, rm0, 1));
        rm0 = fmaxf(rm0, __shfl_xor_sync(0xffffffffu, rm0, 2));
        rm1 = fmaxf(rm1, __shfl_xor_sync(0xffffffffu, rm1, 1));
        rm1 = fmaxf(rm1, __shfl_xor_sync(0xffffffffu, rm1, 2));
        float mn0 = fmaxf(m0, rm0), mn1 = fmaxf(m1, rm1);
        float f0 = __expf(m0 - mn0), f1 = __expf(m1 - mn1);
        float sum0 = 0.f, sum1 = 0.f;
#pragma unroll
        for (int j = 0; j < 8; j++) {
            float p0 = __expf(c[j][0] - mn0); c[j][0] = p0; sum0 += p0;
            float p1 = __expf(c[j][1] - mn0); c[j][1] = p1; sum0 += p1;
            float p2 = __expf(c[j][2] - mn1); c[j][2] = p2; sum1 += p2;
            float p3 = __expf(c[j][3] - mn1); c[j][3] = p3; sum1 += p3;
        }
        sum0 += __shfl_xor_sync(0xffffffffu, sum0, 1);
        sum0 += __shfl_xor_sync(0xffffffffu, sum0, 2);
        sum1 += __shfl_xor_sync(0xffffffffu, sum1, 1);
        sum1 += __shfl_xor_sync(0xffffffffu, sum1, 2);
        l0 = l0 * f0 + sum0; l1 = l1 * f1 + sum1;
        m0 = mn0; m1 = mn1;
#pragma unroll
        for (int j = 0; j < 8; j++) {
            o[j][0] *= f0; o[j][1] *= f0;
            o[j][2] *= f1; o[j][3] *= f1;
        }

#pragma unroll
        for (int kk = 0; kk < 4; kk++) {
            const int ja = kk * 2, jb = kk * 2 + 1;
            uint32_t ph0, ph1, ph2, ph3, pl0, pl1, pl2, pl3;
            make_hl(c[ja][0], c[ja][1], ph0, pl0);
            make_hl(c[ja][2], c[ja][3], ph1, pl1);
            make_hl(c[jb][0], c[jb][1], ph2, pl2);
            make_hl(c[jb][2], c[jb][3], ph3, pl3);
#pragma unroll
            for (int jd = 0; jd < 8; jd++) {
                uint32_t voff = SWZ128((uint32_t)((kk * 16 + (lane & 15)) * 128 + jd * 16));
                uint32_t vh0, vh1, vl0, vl1;
                ldsm_x2_t(vh0, vh1, sbase + AT_VH + voff);
                ldsm_x2_t(vl0, vl1, sbase + AT_VL + voff);
                mma16816_bf(o[jd][0], o[jd][1], o[jd][2], o[jd][3], ph0, ph1, ph2, ph3, vh0, vh1);
                mma16816_bf(o[jd][0], o[jd][1], o[jd][2], o[jd][3], ph0, ph1, ph2, ph3, vl0, vl1);
                mma16816_bf(o[jd][0], o[jd][1], o[jd][2], o[jd][3], pl0, pl1, pl2, pl3, vh0, vh1);
            }
        }
    }

    float inv0 = 1.f / l0, inv1 = 1.f / l1;
    size_t row0 = (size_t)b * 1024 + t0 + wid * 16 + r0;
    size_t row1 = row0 + 8;
#pragma unroll
    for (int jd = 0; jd < 8; jd++) {
        int colg = hd * HDIM + jd * 8 + qcol2;
        uint32_t h, lz;
        make_hl(o[jd][0] * inv0, o[jd][1] * inv0, h, lz);
        *(uint32_t*)(g_aoh + row0 * 1024 + colg) = h;
        *(uint32_t*)(g_aol + row0 * 1024 + colg) = lz;
        make_hl(o[jd][2] * inv1, o[jd][3] * inv1, h, lz);
        *(uint32_t*)(g_aoh + row1 * 1024 + colg) = h;
        *(uint32_t*)(g_aol + row1 * 1024 + colg) = lz;
    }
}

// ---------------------------------------------------------------------------
// Projection GEMM, bf16 3-term (unchanged from passing R12)
// ---------------------------------------------------------------------------
#define PROJ_SMEM_BYTES (131072 + 1024)

__global__ __launch_bounds__(256, 1) void proj_gemm_kernel(
    const float* __restrict__ bo, float* __restrict__ out)
{
    extern __shared__ char dynp[];
    const uint32_t base = (smem_u32(dynp) + 1023u) & ~1023u;

    const int tid = threadIdx.x;
    const int wid = tid >> 5, lane = tid & 31;
    const int j0 = blockIdx.x * 128;
    const int m0 = blockIdx.y * 128;
    const int wm = wid & 1;
    const int wn = wid >> 1;

    const __nv_bfloat16* bases[4] = {
        g_aoh + (size_t)m0 * 1024,
        g_aol + (size_t)m0 * 1024,
        g_woh + (size_t)j0 * 1024,
        g_wol + (size_t)j0 * 1024,
    };

    auto fill = [&](int bsel, int k0) {
#pragma unroll
        for (int j = 0; j < 16; j++) {
            const int sub = j >> 2;
            int qq = tid + 256 * (j & 3);
            int r = qq >> 3, c16 = qq & 7;
            uint32_t off = (uint32_t)(r * 128 + c16 * 16);
            uint32_t dst = base + (uint32_t)bsel * 65536u + (uint32_t)sub * 16384u + SWZ128(off);
            const void* src = (const void*)(bases[sub] + (size_t)r * 1024 + k0 + c16 * 8);
            asm volatile("cp.async.cg.shared.global [%0], [%1], 16;" :: "r"(dst), "l"(src));
        }
        asm volatile("cp.async.commit_group;");
    };

    float acc[4][4][4];
#pragma unroll
    for (int i = 0; i < 4; i++)
#pragma unroll
        for (int j = 0; j < 4; j++)
#pragma unroll
            for (int e = 0; e < 4; e++) acc[i][j][e] = 0.f;

    const int a_r  = lane & 15;
    const int a_c8 = (lane >> 4) * 8;
    const int b_r  = lane & 7;
    const int b_c8 = ((lane >> 3) & 1) * 8;

    fill(0, 0);

    for (int s = 0; s < 16; s++) {
        const int bsel = s & 1;
        if (s + 1 < 16) {
            fill(bsel ^ 1, (s + 1) * 64);
            asm volatile("cp.async.wait_group 1;");
        } else {
            asm volatile("cp.async.wait_group 0;");
        }
        __syncthreads();

        const uint32_t bb  = base + (uint32_t)bsel * 65536u;
        const uint32_t bAh = bb;
        const uint32_t bAl = bb + 16384u;
        const uint32_t bBh = bb + 32768u;
        const uint32_t bBl = bb + 49152u;

#pragma unroll
        for (int kc = 0; kc < 64; kc += 16) {
            uint32_t ah[4][4], al[4][4];
#pragma unroll
            for (int i = 0; i < 4; i++) {
                uint32_t off = (uint32_t)((wm * 64 + i * 16 + a_r) * 128 + (kc + a_c8) * 2);
                uint32_t sw = SWZ128(off);
                ldsm_x4(ah[i][0], ah[i][1], ah[i][2], ah[i][3], bAh + sw);
                ldsm_x4(al[i][0], al[i][1], al[i][2], al[i][3], bAl + sw);
            }
            uint32_t bh[4][2], bl[4][2];
#pragma unroll
            for (int j = 0; j < 4; j++) {
                uint32_t off = (uint32_t)((wn * 32 + j * 8 + b_r) * 128 + (kc + b_c8) * 2);
                uint32_t sw = SWZ128(off);
                ldsm_x2(bh[j][0], bh[j][1], bBh + sw);
                ldsm_x2(bl[j][0], bl[j][1], bBl + sw);
            }
#pragma unroll
            for (int i = 0; i < 4; i++)
#pragma unroll
                for (int j = 0; j < 4; j++) {
                    mma16816_bf(acc[i][j][0], acc[i][j][1], acc[i][j][2], acc[i][j][3],
                                ah[i][0], ah[i][1], ah[i][2], ah[i][3], bh[j][0], bh[j][1]);
                    mma16816_bf(acc[i][j][0], acc[i][j][1], acc[i][j][2], acc[i][j][3],
                                ah[i][0], ah[i][1], ah[i][2], ah[i][3], bl[j][0], bl[j][1]);
                    mma16816_bf(acc[i][j][0], acc[i][j][1], acc[i][j][2], acc[i][j][3],
                                al[i][0], al[i][1], al[i][2], al[i][3], bh[j][0], bh[j][1]);
                }
        }
        __syncthreads();
    }

    const int cr = lane >> 2;
    const int cc = (lane & 3) * 2;
#pragma unroll
    for (int i = 0; i < 4; i++) {
        const int r_lo = m0 + wm * 64 + i * 16 + cr;
        const int r_hi = r_lo + 8;
#pragma unroll
        for (int j = 0; j < 4; j++) {
            const int p = j0 + wn * 32 + j * 8 + cc;
            float2 bb = *(const float2*)(bo + p);
            float2 v0 = {acc[i][j][0] + bb.x, acc[i][j][1] + bb.y};
            float2 v1 = {acc[i][j][2] + bb.x, acc[i][j][3] + bb.y};
            *(float2*)(out + (size_t)r_lo * 1024 + p) = v0;
            *(float2*)(out + (size_t)r_hi * 1024 + p) = v1;
        }
    }
}

// ---------------------------------------------------------------------------
extern "C" void kernel_launch(void* const* d_in, const int* in_sizes, int n_in,
                              void* d_out, int out_size)
{
    const float* q   = (const float*)d_in[0];
    const float* k   = (const float*)d_in[1];
    const float* v   = (const float*)d_in[2];
    const float* Wq  = (const float*)d_in[3];
    const float* bq  = (const float*)d_in[4];
    const float* Wk  = (const float*)d_in[5];
    const float* bk  = (const float*)d_in[6];
    const float* Wv  = (const float*)d_in[7];
    const float* bv  = (const float*)d_in[8];
    const float* Wo  = (const float*)d_in[9];
    const float* bo  = (const float*)d_in[10];
    const int*   mask = (const int*)d_in[11];
    float* out = (float*)d_out;

    cudaFuncSetAttribute(conv_gemm_kernel,
                         cudaFuncAttributeMaxDynamicSharedMemorySize, GEMM_SMEM_BYTES);
    cudaFuncSetAttribute(attn_mma_kernel,
                         cudaFuncAttributeMaxDynamicSharedMemorySize, ATTN_SMEM_BYTES);
    cudaFuncSetAttribute(proj_gemm_kernel,
                         cudaFuncAttributeMaxDynamicSharedMemorySize, PROJ_SMEM_BYTES);

    prep_a_kernel<<<dim3(1024, 3), 256>>>(Wq, Wk, Wv);
    prep_b_kernel<<<dim3(128, 24), 256>>>(q, k, v);
    wo_prep_kernel<<<1024, 256>>>(Wo);
    conv_gemm_kernel<<<dim3(8, 8, 24), 128, GEMM_SMEM_BYTES>>>(bq, bk, bv);
    attn_mma_kernel<<<dim3(8, 16, 8), 256, ATTN_SMEM_BYTES>>>(mask);
    proj_gemm_kernel<<<dim3(8, 64), 256, PROJ_SMEM_BYTES>>>(bo, out);
}

// round 15
// speedup vs baseline: 11.6635x; 1.0020x over previous
#include <cuda_runtime.h>
#include <cuda_fp16.h>
#include <cuda_bf16.h>
#include <cstdint>
#include <math.h>

#define DIMC 1024
#define BATCH 8
#define NHEADS 16
#define HDIM 64

// ---------------------------------------------------------------------------
// Scratch (static device arrays: allocation-free rule)
// ---------------------------------------------------------------------------
__device__ float g_qc[BATCH * DIMC * DIMC];
__device__ float g_kc[BATCH * DIMC * DIMC];
__device__ float g_vc[BATCH * DIMC * DIMC];

// fp16 conv operands (unchanged — conv error stays bit-identical)
__device__ __half g_W16[3ULL * 1024 * 9216];
__device__ __half g_B16[24ULL * 1024 * 9216];

// bf16 hi/lo attention output (A of projection), [b*1024+t][1024]
__device__ __nv_bfloat16 g_aoh[BATCH * DIMC * DIMC];
__device__ __nv_bfloat16 g_aol[BATCH * DIMC * DIMC];
// bf16 hi/lo Wo, [j][c]
__device__ __nv_bfloat16 g_woh[DIMC * DIMC];
__device__ __nv_bfloat16 g_wol[DIMC * DIMC];

// ---------------------------------------------------------------------------
// Helpers (portable sm_80+ PTX only — tcgen05 rejected by this build's ptxas
// target sm_103 [no 'a']; ldmatrix + mma.sync HMMA path instead)
// ---------------------------------------------------------------------------
__device__ __forceinline__ uint32_t smem_u32(const void* p) {
    uint32_t a;
    asm("{ .reg .u64 t; cvta.to.shared.u64 t, %1; cvt.u32.u64 %0, t; }" : "=r"(a) : "l"(p));
    return a;
}

#define SWZ128(off) ((off) ^ (((off) >> 3) & 0x70))

__device__ __forceinline__ void ldsm_x4(uint32_t &r0, uint32_t &r1, uint32_t &r2, uint32_t &r3,
                                        uint32_t addr) {
    asm volatile("ldmatrix.sync.aligned.m8n8.x4.shared.b16 {%0,%1,%2,%3}, [%4];"
                 : "=r"(r0), "=r"(r1), "=r"(r2), "=r"(r3) : "r"(addr));
}
__device__ __forceinline__ void ldsm_x2(uint32_t &r0, uint32_t &r1, uint32_t addr) {
    asm volatile("ldmatrix.sync.aligned.m8n8.x2.shared.b16 {%0,%1}, [%2];"
                 : "=r"(r0), "=r"(r1) : "r"(addr));
}
__device__ __forceinline__ void ldsm_x2_t(uint32_t &r0, uint32_t &r1, uint32_t addr) {
    asm volatile("ldmatrix.sync.aligned.m8n8.x2.trans.shared.b16 {%0,%1}, [%2];"
                 : "=r"(r0), "=r"(r1) : "r"(addr));
}
__device__ __forceinline__ void mma16816_f16(float &c0, float &c1, float &c2, float &c3,
                                             uint32_t a0, uint32_t a1, uint32_t a2, uint32_t a3,
                                             uint32_t b0, uint32_t b1) {
    asm volatile("mma.sync.aligned.m16n8k16.row.col.f32.f16.f16.f32 "
                 "{%0,%1,%2,%3}, {%4,%5,%6,%7}, {%8,%9}, {%0,%1,%2,%3};"
                 : "+f"(c0), "+f"(c1), "+f"(c2), "+f"(c3)
                 : "r"(a0), "r"(a1), "r"(a2), "r"(a3), "r"(b0), "r"(b1));
}
__device__ __forceinline__ void mma16816_bf(float &c0, float &c1, float &c2, float &c3,
                                            uint32_t a0, uint32_t a1, uint32_t a2, uint32_t a3,
                                            uint32_t b0, uint32_t b1) {
    asm volatile("mma.sync.aligned.m16n8k16.row.col.f32.bf16.bf16.f32 "
                 "{%0,%1,%2,%3}, {%4,%5,%6,%7}, {%8,%9}, {%0,%1,%2,%3};"
                 : "+f"(c0), "+f"(c1), "+f"(c2), "+f"(c3)
                 : "r"(a0), "r"(a1), "r"(a2), "r"(a3), "r"(b0), "r"(b1));
}

// split 4 f32 -> bf16 hi/lo, store 8B each to shared
__device__ __forceinline__ void split_st8(float4 v, uint32_t addrH, uint32_t addrL) {
    __nv_bfloat16 h0 = __float2bfloat16(v.x), h1 = __float2bfloat16(v.y);
    __nv_bfloat16 h2 = __float2bfloat16(v.z), h3 = __float2bfloat16(v.w);
    uint32_t H0 = (uint32_t)__bfloat16_as_ushort(h0) | ((uint32_t)__bfloat16_as_ushort(h1) << 16);
    uint32_t H1 = (uint32_t)__bfloat16_as_ushort(h2) | ((uint32_t)__bfloat16_as_ushort(h3) << 16);
    float l0 = v.x - __bfloat162float(h0), l1 = v.y - __bfloat162float(h1);
    float l2 = v.z - __bfloat162float(h2), l3 = v.w - __bfloat162float(h3);
    uint32_t L0, L1;
    asm("cvt.rn.bf16x2.f32 %0, %1, %2;" : "=r"(L0) : "f"(l1), "f"(l0));
    asm("cvt.rn.bf16x2.f32 %0, %1, %2;" : "=r"(L1) : "f"(l3), "f"(l2));
    asm volatile("st.shared.v2.u32 [%0], {%1,%2};" :: "r"(addrH), "r"(H0), "r"(H1));
    asm volatile("st.shared.v2.u32 [%0], {%1,%2};" :: "r"(addrL), "r"(L0), "r"(L1));
}

// pack (a,b) -> bf16x2 hi/lo pair regs (a in lo half, b in hi half)
__device__ __forceinline__ void make_hl(float a, float b, uint32_t &h, uint32_t &l) {
    __nv_bfloat16 ha = __float2bfloat16(a), hb = __float2bfloat16(b);
    h = (uint32_t)__bfloat16_as_ushort(ha) | ((uint32_t)__bfloat16_as_ushort(hb) << 16);
    float la = a - __bfloat162float(ha), lb = b - __bfloat162float(hb);
    asm("cvt.rn.bf16x2.f32 %0, %1, %2;" : "=r"(l) : "f"(lb), "f"(la));
}

// ---------------------------------------------------------------------------
// prep_a: W[o][ic*9+t] f32 -> g_W16 [conv][o][t*1024+ic] fp16 (unchanged)
// ---------------------------------------------------------------------------
__global__ __launch_bounds__(256) void prep_a_kernel(
    const float* __restrict__ Wq, const float* __restrict__ Wk, const float* __restrict__ Wv)
{
    __shared__ float row[9216];
    const int conv = blockIdx.y, o = blockIdx.x, tid = threadIdx.x;
    const float* w = (conv == 0) ? Wq : (conv == 1) ? Wk : Wv;
    const float* src = w + (size_t)o * 9216;
    for (int i = tid; i < 9216; i += 256) row[i] = src[i];
    __syncthreads();

    __half* dh = g_W16 + ((size_t)conv * 1024 + o) * 9216;
    for (int g = tid; g < 1152; g += 256) {
        int t = g >> 7;
        int icb = (g & 127) * 8;
        unsigned int hw[4];
#pragma unroll
        for (int pr = 0; pr < 4; pr++) {
            __half h0 = __float2half_rn(row[(icb + pr * 2 + 0) * 9 + t]);
            __half h1 = __float2half_rn(row[(icb + pr * 2 + 1) * 9 + t]);
            hw[pr] = (unsigned)__half_as_ushort(h0) | ((unsigned)__half_as_ushort(h1) << 16);
        }
        uint4 hv4 = {hw[0], hw[1], hw[2], hw[3]};
        *(uint4*)(dh + (size_t)t * 1024 + icb) = hv4;
    }
}

// ---------------------------------------------------------------------------
// prep_b: im2col + fp16 convert (unchanged)
// ---------------------------------------------------------------------------
__global__ __launch_bounds__(256) void prep_b_kernel(
    const float* __restrict__ q, const float* __restrict__ k, const float* __restrict__ v)
{
    __shared__ float Xs[8 * 1024];
    const int cb = blockIdx.y;
    const int ic0 = blockIdx.x * 8;
    const int conv = cb >> 3, b = cb & 7;
    const float* src = ((conv == 0) ? q : (conv == 1) ? k : v) + ((size_t)b * 1024 + ic0) * 1024;
    for (int i = threadIdx.x; i < 8192; i += 256) Xs[i] = src[i];
    __syncthreads();

    __half* bh = g_B16 + (size_t)cb * 1024 * 9216;
    for (int e = threadIdx.x; e < 9216; e += 256) {
        int t = e >> 10;
        int p = e & 1023;
        int y = p >> 5, x = p & 31;
        int r = t / 3, c = t - r * 3;
        int sy = y + r - 1, sx = x + c - 1;
        bool ok = ((unsigned)sy < 32u) && ((unsigned)sx < 32u);
        int so = sy * 32 + sx;
        unsigned int hw[4];
#pragma unroll
        for (int pr = 0; pr < 4; pr++) {
            float v0 = ok ? Xs[(pr * 2 + 0) * 1024 + so] : 0.f;
            float v1 = ok ? Xs[(pr * 2 + 1) * 1024 + so] : 0.f;
            __half h0 = __float2half_rn(v0);
            __half h1 = __float2half_rn(v1);
            hw[pr] = (unsigned)__half_as_ushort(h0) | ((unsigned)__half_as_ushort(h1) << 16);
        }
        uint4 hv4 = {hw[0], hw[1], hw[2], hw[3]};
        *(uint4*)(bh + (size_t)p * 9216 + t * 1024 + ic0) = hv4;
    }
}

// ---------------------------------------------------------------------------
// wo_prep: Wo[j][c] f32 -> g_woh/g_wol bf16 hi/lo. One float4 per thread.
// ---------------------------------------------------------------------------
__global__ __launch_bounds__(256) void wo_prep_kernel(const float* __restrict__ Wo)
{
    const int row = blockIdx.x, tid = threadIdx.x;
    const int c4 = tid * 4;
    float4 v = *(const float4*)(Wo + (size_t)row * 1024 + c4);
    __nv_bfloat16 h0 = __float2bfloat16(v.x), h1 = __float2bfloat16(v.y);
    __nv_bfloat16 h2 = __float2bfloat16(v.z), h3 = __float2bfloat16(v.w);
    uint2 H;
    H.x = (uint32_t)__bfloat16_as_ushort(h0) | ((uint32_t)__bfloat16_as_ushort(h1) << 16);
    H.y = (uint32_t)__bfloat16_as_ushort(h2) | ((uint32_t)__bfloat16_as_ushort(h3) << 16);
    float l0 = v.x - __bfloat162float(h0), l1 = v.y - __bfloat162float(h1);
    float l2 = v.z - __bfloat162float(h2), l3 = v.w - __bfloat162float(h3);
    uint2 L;
    asm("cvt.rn.bf16x2.f32 %0, %1, %2;" : "=r"(L.x) : "f"(l1), "f"(l0));
    asm("cvt.rn.bf16x2.f32 %0, %1, %2;" : "=r"(L.y) : "f"(l3), "f"(l2));
    *(uint2*)(g_woh + (size_t)row * 1024 + c4) = H;
    *(uint2*)(g_wol + (size_t)row * 1024 + c4) = L;
}

// ---------------------------------------------------------------------------
// conv GEMM via mma.sync (HMMA fp16, single term):
// R14: single __syncthreads per slice (wait -> sync -> fill(next) -> MMA;
// top barrier already orders prior reads vs the new fill) and B-frags via
// paired ldsm_x4 (8 LDSM/k-step, was 12). 4 warps, warp tile 64x64,
// CTA 128x128, K-slice 64, double-buffered cp.async, SW128 swizzle.
// grid (8 p, 8 o, 24), 66KB smem, 2 CTAs/SM.
// ---------------------------------------------------------------------------
#define GEMM_SMEM_BYTES (65536 + 1024)
#define NSLICES 144

__global__ __launch_bounds__(128, 2) void conv_gemm_kernel(
    const float* __restrict__ bq, const float* __restrict__ bk, const float* __restrict__ bv)
{
    extern __shared__ char dynsmem[];
    const uint32_t raw = smem_u32(dynsmem);
    const uint32_t base = (raw + 1023u) & ~1023u;

    const int tid = threadIdx.x;
    const int wid = tid >> 5, lane = tid & 31;
    const int p0 = blockIdx.x * 128;
    const int o0 = blockIdx.y * 128;
    const int cb = blockIdx.z;
    const int conv = cb >> 3, b = cb & 7;

    const int wm = wid & 1;          // M group of 64
    const int wn = wid >> 1;         // N group of 64

    const __half* baseA = g_W16 + ((size_t)conv * 1024 + o0) * 9216;
    const __half* baseB = g_B16 + ((size_t)cb * 1024 + p0) * 9216;

    auto fill = [&](int bsel, int k0) {
#pragma unroll
        for (int j = 0; j < 16; j++) {
            const int sub = j >> 3;                 // 0:A 1:B
            int qq = tid + 128 * (j & 7);           // 0..1023 in sub-buffer
            int r = qq >> 3, c16 = qq & 7;          // row 0..127, 16B chunk
            uint32_t off = (uint32_t)(r * 128 + c16 * 16);
            uint32_t dst = base + (uint32_t)bsel * 32768u + (uint32_t)sub * 16384u + SWZ128(off);
            const __half* srcb = (sub == 0) ? baseA : baseB;
            const void* src = (const void*)(srcb + (size_t)r * 9216 + k0 + c16 * 8);
            asm volatile("cp.async.cg.shared.global [%0], [%1], 16;" :: "r"(dst), "l"(src));
        }
        asm volatile("cp.async.commit_group;");
    };

    float acc[4][8][4];
#pragma unroll
    for (int i = 0; i < 4; i++)
#pragma unroll
        for (int j = 0; j < 8; j++)
#pragma unroll
            for (int e = 0; e < 4; e++) acc[i][j][e] = 0.f;

    const int a_r   = lane & 15;
    const int a_c8  = (lane >> 4) * 8;
    const int b_r4  = (lane & 7) | ((lane >> 4) << 3);  // +8 rows for lanes 16-31
    const int b_c8  = ((lane >> 3) & 1) * 8;

    fill(0, 0);

    for (int s = 0; s < NSLICES; s++) {
        const int bsel = s & 1;
        asm volatile("cp.async.wait_group 0;");   // fill(s) is the only pending group
        __syncthreads();                           // also orders slice s-1 reads vs fill below
        if (s + 1 < NSLICES) fill(bsel ^ 1, (s + 1) * 64);

        const uint32_t bb = base + (uint32_t)bsel * 32768u;
        const uint32_t bA = bb;
        const uint32_t bB = bb + 16384u;

#pragma unroll
        for (int kc = 0; kc < 64; kc += 16) {
            uint32_t ah[4][4];
#pragma unroll
            for (int i = 0; i < 4; i++) {
                uint32_t off = (uint32_t)((wm * 64 + i * 16 + a_r) * 128 + (kc + a_c8) * 2);
                ldsm_x4(ah[i][0], ah[i][1], ah[i][2], ah[i][3], bA + SWZ128(off));
            }
            uint32_t bh[8][2];
#pragma unroll
            for (int j2 = 0; j2 < 4; j2++) {       // 2 j-tiles per ldmatrix.x4
                uint32_t off = (uint32_t)((wn * 64 + j2 * 16 + b_r4) * 128 + (kc + b_c8) * 2);
                ldsm_x4(bh[j2 * 2][0], bh[j2 * 2][1], bh[j2 * 2 + 1][0], bh[j2 * 2 + 1][1],
                        bB + SWZ128(off));
            }
#pragma unroll
            for (int i = 0; i < 4; i++)
#pragma unroll
                for (int j = 0; j < 8; j++)
                    mma16816_f16(acc[i][j][0], acc[i][j][1], acc[i][j][2], acc[i][j][3],
                                 ah[i][0], ah[i][1], ah[i][2], ah[i][3], bh[j][0], bh[j][1]);
        }
    }

    float* outp = ((conv == 0) ? g_qc : (conv == 1) ? g_kc : g_vc) + (size_t)b * (DIMC * DIMC);
    const float* bias = (conv == 0) ? bq : (conv == 1) ? bk : bv;
    const int cr = lane >> 2;
    const int cc = (lane & 3) * 2;
#pragma unroll
    for (int i = 0; i < 4; i++) {
        const int o_lo = o0 + wm * 64 + i * 16 + cr;
        const int o_hi = o_lo + 8;
        const float bb0 = bias[o_lo];
        const float bb1 = bias[o_hi];
#pragma unroll
        for (int j = 0; j < 8; j++) {
            const int p = p0 + wn * 64 + j * 8 + cc;
            float2 v0 = {acc[i][j][0] + bb0, acc[i][j][1] + bb0};
            float2 v1 = {acc[i][j][2] + bb1, acc[i][j][3] + bb1};
            *(float2*)(outp + (size_t)o_lo * 1024 + p) = v0;
            *(float2*)(outp + (size_t)o_hi * 1024 + p) = v1;
        }
    }
}

// ---------------------------------------------------------------------------
// Tensor-core flash attention, bf16 3-term (unchanged from passing R13)
// ---------------------------------------------------------------------------
#define AT_QH 0
#define AT_QL 16384
#define AT_KH 32768
#define AT_KL 40960
#define AT_VH 49152
#define AT_VL 57344
#define ATTN_SMEM_BYTES (65536 + 1024)

__global__ __launch_bounds__(256, 2) void attn_mma_kernel(const int* __restrict__ mask)
{
    extern __shared__ char smemc[];
    const uint32_t sbase = (smem_u32(smemc) + 1023u) & ~1023u;

    const int tid = threadIdx.x;
    const int wid = tid >> 5, lane = tid & 31;
    const int t0 = blockIdx.x * 128;
    const int hd = blockIdx.y;
    const int b  = blockIdx.z;

    const float* Qg = g_qc + ((size_t)b * 1024 + t0) * 1024 + hd * HDIM;
    const float* Kg = g_kc + (size_t)b * 1024 * 1024 + hd * HDIM;
    const float* Vg = g_vc + (size_t)b * 1024 * 1024 + hd * HDIM;
    const int* mrow = mask + (size_t)b * 1024 * 1024;

#pragma unroll
    for (int rep = 0; rep < 8; rep++) {
        int idx = tid + 256 * rep;
        int t = idx >> 4;
        int d4 = (idx & 15) * 4;
        float4 qv = *(const float4*)(Qg + (size_t)t * 1024 + d4);
        uint32_t sw = SWZ128((uint32_t)(t * 128 + d4 * 2));
        split_st8(qv, sbase + AT_QH + sw, sbase + AT_QL + sw);
    }

    float m0 = -INFINITY, m1 = -INFINITY, l0 = 0.f, l1 = 0.f;
    float o[8][4];
#pragma unroll
    for (int j = 0; j < 8; j++)
#pragma unroll
        for (int e = 0; e < 4; e++) o[j][e] = 0.f;

    const float scale = 0.125f;
    const int r0 = lane >> 2;
    const int qcol2 = (lane & 3) * 2;

    for (int s0 = 0; s0 < 1024; s0 += 64) {
        __syncthreads();
#pragma unroll
        for (int rep = 0; rep < 4; rep++) {
            int idx = tid + 256 * rep;
            int s = idx >> 4;
            int d4 = (idx & 15) * 4;
            uint32_t sw = SWZ128((uint32_t)(s * 128 + d4 * 2));
            float4 kv = *(const float4*)(Kg + (size_t)(s0 + s) * 1024 + d4);
            split_st8(kv, sbase + AT_KH + sw, sbase + AT_KL + sw);
            float4 vv = *(const float4*)(Vg + (size_t)(s0 + s) * 1024 + d4);
            split_st8(vv, sbase + AT_VH + sw, sbase + AT_VL + sw);
        }
        __syncthreads();

        float c[8][4];
#pragma unroll
        for (int j = 0; j < 8; j++)
#pragma unroll
            for (int e = 0; e < 4; e++) c[j][e] = 0.f;

#pragma unroll
        for (int kc = 0; kc < 64; kc += 16) {
            uint32_t aoff = SWZ128((uint32_t)((wid * 16 + (lane & 15)) * 128 + (kc + (lane >> 4) * 8) * 2));
            uint32_t ah0, ah1, ah2, ah3, al0, al1, al2, al3;
            ldsm_x4(ah0, ah1, ah2, ah3, sbase + AT_QH + aoff);
            ldsm_x4(al0, al1, al2, al3, sbase + AT_QL + aoff);
#pragma unroll
            for (int j = 0; j < 8; j++) {
                uint32_t boff = SWZ128((uint32_t)((j * 8 + (lane & 7)) * 128 + (kc + ((lane >> 3) & 1) * 8) * 2));
                uint32_t kh0, kh1, kl0, kl1;
                ldsm_x2(kh0, kh1, sbase + AT_KH + boff);
                ldsm_x2(kl0, kl1, sbase + AT_KL + boff);
                mma16816_bf(c[j][0], c[j][1], c[j][2], c[j][3], ah0, ah1, ah2, ah3, kh0, kh1);
                mma16816_bf(c[j][0], c[j][1], c[j][2], c[j][3], ah0, ah1, ah2, ah3, kl0, kl1);
                mma16816_bf(c[j][0], c[j][1], c[j][2], c[j][3], al0, al1, al2, al3, kh0, kh1);
            }
        }

        const int trg0 = t0 + wid * 16 + r0;
        const int* mr0 = mrow + (size_t)trg0 * 1024;
        const int* mr1 = mr0 + 8 * 1024;
#pragma unroll
        for (int j = 0; j < 8; j++) {
            int colg = s0 + j * 8 + qcol2;
            int2 q0 = *(const int2*)(mr0 + colg);
            int2 q1 = *(const int2*)(mr1 + colg);
            c[j][0] = q0.x ? c[j][0] * scale : -1e9f;
            c[j][1] = q0.y ? c[j][1] * scale : -1e9f;
            c[j][2] = q1.x ? c[j][2] * scale : -1e9f;
            c[j][3] = q1.y ? c[j][3] * scale : -1e9f;
        }

        float rm0 = -INFINITY, rm1 = -INFINITY;
#pragma unroll
        for (int j = 0; j < 8; j++) {
            rm0 = fmaxf(rm0, fmaxf(c[j][0], c[j][1]));
            rm1 = fmaxf(rm1, fmaxf(c[j][2], c[j][3]));
        }
        rm0 = fmaxf(rm0, __shfl_xor_sync(0xffffffffu, rm0, 1));
        rm0 = fmaxf(rm0, __shfl_xor_sync(0xffffffffu, rm0, 2));
        rm1 = fmaxf(rm1, __shfl_xor_sync(0xffffffffu, rm1, 1));
        rm1 = fmaxf(rm1, __shfl_xor_sync(0xffffffffu, rm1, 2));
        float mn0 = fmaxf(m0, rm0), mn1 = fmaxf(m1, rm1);
        float f0 = __expf(m0 - mn0), f1 = __expf(m1 - mn1);
        float sum0 = 0.f, sum1 = 0.f;
#pragma unroll
        for (int j = 0; j < 8; j++) {
            float p0 = __expf(c[j][0] - mn0); c[j][0] = p0; sum0 += p0;
            float p1 = __expf(c[j][1] - mn0); c[j][1] = p1; sum0 += p1;
            float p2 = __expf(c[j][2] - mn1); c[j][2] = p2; sum1 += p2;
            float p3 = __expf(c[j][3] - mn1); c[j][3] = p3; sum1 += p3;
        }
        sum0 += __shfl_xor_sync(0xffffffffu, sum0, 1);
        sum0 += __shfl_xor_sync(0xffffffffu, sum0, 2);
        sum1 += __shfl_xor_sync(0xffffffffu, sum1, 1);
        sum1 += __shfl_xor_sync(0xffffffffu, sum1, 2);
        l0 = l0 * f0 + sum0; l1 = l1 * f1 + sum1;
        m0 = mn0; m1 = mn1;
#pragma unroll
        for (int j = 0; j < 8; j++) {
            o[j][0] *= f0; o[j][1] *= f0;
            o[j][2] *= f1; o[j][3] *= f1;
        }

#pragma unroll
        for (int kk = 0; kk < 4; kk++) {
            const int ja = kk * 2, jb = kk * 2 + 1;
            uint32_t ph0, ph1, ph2, ph3, pl0, pl1, pl2, pl3;
            make_hl(c[ja][0], c[ja][1], ph0, pl0);
            make_hl(c[ja][2], c[ja][3], ph1, pl1);
            make_hl(c[jb][0], c[jb][1], ph2, pl2);
            make_hl(c[jb][2], c[jb][3], ph3, pl3);
#pragma unroll
            for (int jd = 0; jd < 8; jd++) {
                uint32_t voff = SWZ128((uint32_t)((kk * 16 + (lane & 15)) * 128 + jd * 16));
                uint32_t vh0, vh1, vl0, vl1;
                ldsm_x2_t(vh0, vh1, sbase + AT_VH + voff);
                ldsm_x2_t(vl0, vl1, sbase + AT_VL + voff);
                mma16816_bf(o[jd][0], o[jd][1], o[jd][2], o[jd][3], ph0, ph1, ph2, ph3, vh0, vh1);
                mma16816_bf(o[jd][0], o[jd][1], o[jd][2], o[jd][3], ph0, ph1, ph2, ph3, vl0, vl1);
                mma16816_bf(o[jd][0], o[jd][1], o[jd][2], o[jd][3], pl0, pl1, pl2, pl3, vh0, vh1);
            }
        }
    }

    float inv0 = 1.f / l0, inv1 = 1.f / l1;
    size_t row0 = (size_t)b * 1024 + t0 + wid * 16 + r0;
    size_t row1 = row0 + 8;
#pragma unroll
    for (int jd = 0; jd < 8; jd++) {
        int colg = hd * HDIM + jd * 8 + qcol2;
        uint32_t h, lz;
        make_hl(o[jd][0] * inv0, o[jd][1] * inv0, h, lz);
        *(uint32_t*)(g_aoh + row0 * 1024 + colg) = h;
        *(uint32_t*)(g_aol + row0 * 1024 + colg) = lz;
        make_hl(o[jd][2] * inv1, o[jd][3] * inv1, h, lz);
        *(uint32_t*)(g_aoh + row1 * 1024 + colg) = h;
        *(uint32_t*)(g_aol + row1 * 1024 + colg) = lz;
    }
}

// ---------------------------------------------------------------------------
// Projection GEMM, bf16 3-term. R14: single-sync mainloop (same argument as
// conv). Tile 128x128, K=1024 in 16 slices of 64, double-buffered cp.async.
// grid (8 j-tiles, 64 m-tiles), 256 thr, 129KB smem.
// ---------------------------------------------------------------------------
#define PROJ_SMEM_BYTES (131072 + 1024)

__global__ __launch_bounds__(256, 1) void proj_gemm_kernel(
    const float* __restrict__ bo, float* __restrict__ out)
{
    extern __shared__ char dynp[];
    const uint32_t base = (smem_u32(dynp) + 1023u) & ~1023u;

    const int tid = threadIdx.x;
    const int wid = tid >> 5, lane = tid & 31;
    const int j0 = blockIdx.x * 128;
    const int m0 = blockIdx.y * 128;
    const int wm = wid & 1;
    const int wn = wid >> 1;

    const __nv_bfloat16* bases[4] = {
        g_aoh + (size_t)m0 * 1024,
        g_aol + (size_t)m0 * 1024,
        g_woh + (size_t)j0 * 1024,
        g_wol + (size_t)j0 * 1024,
    };

    auto fill = [&](int bsel, int k0) {
#pragma unroll
        for (int j = 0; j < 16; j++) {
            const int sub = j >> 2;
            int qq = tid + 256 * (j & 3);
            int r = qq >> 3, c16 = qq & 7;
            uint32_t off = (uint32_t)(r * 128 + c16 * 16);
            uint32_t dst = base + (uint32_t)bsel * 65536u + (uint32_t)sub * 16384u + SWZ128(off);
            const void* src = (const void*)(bases[sub] + (size_t)r * 1024 + k0 + c16 * 8);
            asm volatile("cp.async.cg.shared.global [%0], [%1], 16;" :: "r"(dst), "l"(src));
        }
        asm volatile("cp.async.commit_group;");
    };

    float acc[4][4][4];
#pragma unroll
    for (int i = 0; i < 4; i++)
#pragma unroll
        for (int j = 0; j < 4; j++)
#pragma unroll
            for (int e = 0; e < 4; e++) acc[i][j][e] = 0.f;

    const int a_r  = lane & 15;
    const int a_c8 = (lane >> 4) * 8;
    const int b_r  = lane & 7;
    const int b_c8 = ((lane >> 3) & 1) * 8;

    fill(0, 0);

    for (int s = 0; s < 16; s++) {
        const int bsel = s & 1;
        asm volatile("cp.async.wait_group 0;");
        __syncthreads();
        if (s + 1 < 16) fill(bsel ^ 1, (s + 1) * 64);

        const uint32_t bb  = base + (uint32_t)bsel * 65536u;
        const uint32_t bAh = bb;
        const uint32_t bAl = bb + 16384u;
        const uint32_t bBh = bb + 32768u;
        const uint32_t bBl = bb + 49152u;

#pragma unroll
        for (int kc = 0; kc < 64; kc += 16) {
            uint32_t ah[4][4], al[4][4];
#pragma unroll
            for (int i = 0; i < 4; i++) {
                uint32_t off = (uint32_t)((wm * 64 + i * 16 + a_r) * 128 + (kc + a_c8) * 2);
                uint32_t sw = SWZ128(off);
                ldsm_x4(ah[i][0], ah[i][1], ah[i][2], ah[i][3], bAh + sw);
                ldsm_x4(al[i][0], al[i][1], al[i][2], al[i][3], bAl + sw);
            }
            uint32_t bh[4][2], bl[4][2];
#pragma unroll
            for (int j = 0; j < 4; j++) {
                uint32_t off = (uint32_t)((wn * 32 + j * 8 + b_r) * 128 + (kc + b_c8) * 2);
                uint32_t sw = SWZ128(off);
                ldsm_x2(bh[j][0], bh[j][1], bBh + sw);
                ldsm_x2(bl[j][0], bl[j][1], bBl + sw);
            }
#pragma unroll
            for (int i = 0; i < 4; i++)
#pragma unroll
                for (int j = 0; j < 4; j++) {
                    mma16816_bf(acc[i][j][0], acc[i][j][1], acc[i][j][2], acc[i][j][3],
                                ah[i][0], ah[i][1], ah[i][2], ah[i][3], bh[j][0], bh[j][1]);
                    mma16816_bf(acc[i][j][0], acc[i][j][1], acc[i][j][2], acc[i][j][3],
                                ah[i][0], ah[i][1], ah[i][2], ah[i][3], bl[j][0], bl[j][1]);
                    mma16816_bf(acc[i][j][0], acc[i][j][1], acc[i][j][2], acc[i][j][3],
                                al[i][0], al[i][1], al[i][2], al[i][3], bh[j][0], bh[j][1]);
                }
        }
    }

    const int cr = lane >> 2;
    const int cc = (lane & 3) * 2;
#pragma unroll
    for (int i = 0; i < 4; i++) {
        const int r_lo = m0 + wm * 64 + i * 16 + cr;
        const int r_hi = r_lo + 8;
#pragma unroll
        for (int j = 0; j < 4; j++) {
            const int p = j0 + wn * 32 + j * 8 + cc;
            float2 bb = *(const float2*)(bo + p);
            float2 v0 = {acc[i][j][0] + bb.x, acc[i][j][1] + bb.y};
            float2 v1 = {acc[i][j][2] + bb.x, acc[i][j][3] + bb.y};
            *(float2*)(out + (size_t)r_lo * 1024 + p) = v0;
            *(float2*)(out + (size_t)r_hi * 1024 + p) = v1;
        }
    }
}

// ---------------------------------------------------------------------------
extern "C" void kernel_launch(void* const* d_in, const int* in_sizes, int n_in,
                              void* d_out, int out_size)
{
    const float* q   = (const float*)d_in[0];
    const float* k   = (const float*)d_in[1];
    const float* v   = (const float*)d_in[2];
    const float* Wq  = (const float*)d_in[3];
    const float* bq  = (const float*)d_in[4];
    const float* Wk  = (const float*)d_in[5];
    const float* bk  = (const float*)d_in[6];
    const float* Wv  = (const float*)d_in[7];
    const float* bv  = (const float*)d_in[8];
    const float* Wo  = (const float*)d_in[9];
    const float* bo  = (const float*)d_in[10];
    const int*   mask = (const int*)d_in[11];
    float* out = (float*)d_out;

    cudaFuncSetAttribute(conv_gemm_kernel,
                         cudaFuncAttributeMaxDynamicSharedMemorySize, GEMM_SMEM_BYTES);
    cudaFuncSetAttribute(attn_mma_kernel,
                         cudaFuncAttributeMaxDynamicSharedMemorySize, ATTN_SMEM_BYTES);
    cudaFuncSetAttribute(proj_gemm_kernel,
                         cudaFuncAttributeMaxDynamicSharedMemorySize, PROJ_SMEM_BYTES);

    prep_a_kernel<<<dim3(1024, 3), 256>>>(Wq, Wk, Wv);
    prep_b_kernel<<<dim3(128, 24), 256>>>(q, k, v);
    wo_prep_kernel<<<1024, 256>>>(Wo);
    conv_gemm_kernel<<<dim3(8, 8, 24), 128, GEMM_SMEM_BYTES>>>(bq, bk, bv);
    attn_mma_kernel<<<dim3(8, 16, 8), 256, ATTN_SMEM_BYTES>>>(mask);
    proj_gemm_kernel<<<dim3(8, 64), 256, PROJ_SMEM_BYTES>>>(bo, out);
}